// round 2
// baseline (speedup 1.0000x reference)
#include <cuda_runtime.h>
#include <cstdint>

// ---------------- problem constants ----------------
#define BATCH 2
#define DDIM  8
#define HPX   56
#define WPX   56
#define CDIM  256
#define NTOK  (BATCH*DDIM*HPX*WPX)   // 50176
#define NWIN  98                     // (8/4)*(56/8)*(56/8)
#define NBIAS 1575                   // 7*15*15
#define MLPD  1024

// ---------------- scratch (static device allocs are allowed) ----------------
__device__ float g_y  [NTOK*CDIM];     // activations, channel-last
__device__ float g_xn [NTOK*CDIM];     // layernorm output
__device__ float g_qkv[NTOK*3*CDIM];   // qkv projections
__device__ float g_att[NTOK*CDIM];     // attention output (pre out-proj)
__device__ float g_h  [NTOK*MLPD];     // mlp hidden

// ---------------- helpers ----------------
__device__ __forceinline__ float gelu_tanh(float x){
    float x3 = x*x*x;
    return 0.5f*x*(1.f + tanhf(0.7978845608028654f*(x + 0.044715f*x3)));
}

// ---------------- patch embed: conv (1,4,4) stride (1,4,4) ----------------
__global__ void patch_embed_kernel(const float* __restrict__ x,
                                   const float* __restrict__ w,
                                   const float* __restrict__ b,
                                   float* __restrict__ y)
{
    int t = blockIdx.x;
    int wp = t % WPX, hp = (t/WPX) % HPX, d = (t/(WPX*HPX)) % DDIM, bb = t/(WPX*HPX*DDIM);
    __shared__ float patch[64];
    int tid = threadIdx.x;
    if (tid < 64){
        int ic = tid>>4, kh = (tid>>2)&3, kw = tid&3;
        patch[tid] = x[ (((size_t)(bb*4+ic)*DDIM + d)*224 + hp*4+kh)*224 + wp*4+kw ];
    }
    __syncthreads();
    float acc = b[tid];
    const float* wr = w + tid*64;  // (DIM, IC*1*4*4) contiguous
    #pragma unroll
    for (int k=0;k<64;k++) acc += patch[k]*wr[k];
    y[(size_t)t*CDIM + tid] = acc;
}

// ---------------- layernorm: one block per token, 256 threads ----------------
__global__ void ln_kernel(const float* __restrict__ in, float* __restrict__ out,
                          const float* __restrict__ sc, const float* __restrict__ bi)
{
    int t = blockIdx.x, c = threadIdx.x;
    float v = in[(size_t)t*CDIM + c];
    float s1 = v, s2 = v*v;
    #pragma unroll
    for (int o=16;o;o>>=1){
        s1 += __shfl_xor_sync(0xffffffffu, s1, o);
        s2 += __shfl_xor_sync(0xffffffffu, s2, o);
    }
    __shared__ float r1[8], r2[8];
    if ((c&31)==0){ r1[c>>5]=s1; r2[c>>5]=s2; }
    __syncthreads();
    s1 = 0.f; s2 = 0.f;
    #pragma unroll
    for (int k=0;k<8;k++){ s1 += r1[k]; s2 += r2[k]; }
    float mean = s1*(1.f/256.f);
    float var  = s2*(1.f/256.f) - mean*mean;
    float rs = rsqrtf(var + 1e-5f);
    out[(size_t)t*CDIM + c] = (v-mean)*rs*sc[c] + bi[c];
}

// ---------------- generic fp32 SGEMM 128x128x8, 8x8 microtile ----------------
// A:[N,K] row-major, B:[K,M] row-major, C:[N,M]
// MODE 0: C = A@B (+bias if non-null)
// MODE 1: C = gelu(A@B + bias)
// MODE 2: C = C + A@B + bias   (residual accumulate in place)
template<int MODE>
__global__ void sgemm_kernel(const float* __restrict__ A, const float* __restrict__ B,
                             const float* __restrict__ bias, float* C, int M, int K)
{
    __shared__ float As[8][128];
    __shared__ float Bs[8][128];
    int tid = threadIdx.x;
    int row0 = blockIdx.y*128, col0 = blockIdx.x*128;
    int tx = tid & 15, ty = tid >> 4;

    float acc[8][8];
    #pragma unroll
    for (int i=0;i<8;i++)
        #pragma unroll
        for (int j=0;j<8;j++) acc[i][j]=0.f;

    int ar = tid>>1, ak = (tid&1)*4;
    int bk = tid>>5, bc = (tid&31)*4;
    const float* Aptr = A + (size_t)(row0+ar)*K + ak;
    const float* Bptr = B + (size_t)bk*M + col0 + bc;

    for (int k0=0; k0<K; k0+=8){
        float4 av = *(const float4*)(Aptr + k0);
        As[ak+0][ar]=av.x; As[ak+1][ar]=av.y; As[ak+2][ar]=av.z; As[ak+3][ar]=av.w;
        float4 bv = *(const float4*)(Bptr + (size_t)k0*M);
        *(float4*)&Bs[bk][bc] = bv;
        __syncthreads();
        #pragma unroll
        for (int kk=0;kk<8;kk++){
            float4 a0 = *(const float4*)&As[kk][ty*4];
            float4 a1 = *(const float4*)&As[kk][ty*4+64];
            float4 b0 = *(const float4*)&Bs[kk][tx*4];
            float4 b1 = *(const float4*)&Bs[kk][tx*4+64];
            float ar8[8] = {a0.x,a0.y,a0.z,a0.w,a1.x,a1.y,a1.z,a1.w};
            float br8[8] = {b0.x,b0.y,b0.z,b0.w,b1.x,b1.y,b1.z,b1.w};
            #pragma unroll
            for (int i2=0;i2<8;i2++)
                #pragma unroll
                for (int j2=0;j2<8;j2++)
                    acc[i2][j2] += ar8[i2]*br8[j2];
        }
        __syncthreads();
    }

    #pragma unroll
    for (int iq=0;iq<2;iq++)
    #pragma unroll
    for (int ii=0;ii<4;ii++){
        int row = row0 + ty*4 + iq*64 + ii;
        #pragma unroll
        for (int jq=0;jq<2;jq++){
            int col = col0 + tx*4 + jq*64;
            float4 r;
            r.x = acc[iq*4+ii][jq*4+0];
            r.y = acc[iq*4+ii][jq*4+1];
            r.z = acc[iq*4+ii][jq*4+2];
            r.w = acc[iq*4+ii][jq*4+3];
            if (bias){
                r.x += bias[col+0]; r.y += bias[col+1];
                r.z += bias[col+2]; r.w += bias[col+3];
            }
            if (MODE==1){
                r.x = gelu_tanh(r.x); r.y = gelu_tanh(r.y);
                r.z = gelu_tanh(r.z); r.w = gelu_tanh(r.w);
            }
            float* cp = C + (size_t)row*M + col;
            if (MODE==2){
                float4 old = *(const float4*)cp;
                r.x += old.x; r.y += old.y; r.z += old.z; r.w += old.w;
            }
            *(float4*)cp = r;
        }
    }
}

// ---------------- fused window attention ----------------
// grid (B*NWIN, 8 heads), 256 threads = 256 queries of one window.
// Shift handled by index arithmetic; rel-pos bias and shift mask computed on the fly.
__global__ void attn_kernel(const float* __restrict__ qkv,
                            const float* __restrict__ btab_g,   // (NBIAS, 8) for this layer
                            float* __restrict__ att, int shifted)
{
    extern __shared__ float4 sm[];
    float4* Ks = sm;               // 256 rows * 9 float4 (pad -> conflict-free)
    float4* Vs = sm + 256*9;
    float*  btab = (float*)(Vs + 256*9);
    int*    sreg = (int*)(btab + NBIAS);

    int head = blockIdx.y;
    int bw = blockIdx.x;
    int b = bw / NWIN, w = bw % NWIN;
    int wd = w/49, wh = (w/7)%7, ww = w%7;
    int i = threadIdx.x;
    int di = i>>6, hi = (i>>3)&7, wi = i&7;
    int dr = wd*4+di, hr = wh*8+hi, wr = ww*8+wi;   // coords in rolled frame

    // region id for shift mask (computed in rolled-frame coords, like the reference img labels)
    int rd = dr<4?0:(dr<6?1:2);
    int rh = hr<48?0:(hr<52?1:2);
    int rw = wr<48?0:(wr<52?1:2);
    int myreg = rd*9 + rh*3 + rw;
    sreg[i] = myreg;

    // source token (undo the roll by -SHIFT == gather at +SHIFT)
    int d = dr, h = hr, w2 = wr;
    if (shifted){ d = (dr+2)&7; h = (hr+4)%HPX; w2 = (wr+4)%WPX; }
    int tok = ((b*DDIM + d)*HPX + h)*WPX + w2;

    const float4* base = (const float4*)(qkv + (size_t)tok*768 + head*32);
    float4 q[8];
    #pragma unroll
    for (int k=0;k<8;k++){
        q[k]      = base[k];        // Q at +0 floats
        Ks[i*9+k] = base[64+k];     // K at +256 floats
        Vs[i*9+k] = base[128+k];    // V at +512 floats
    }
    for (int t=i; t<NBIAS; t+=256) btab[t] = btab_g[t*8 + head];
    __syncthreads();

    float m = -1e30f, l = 0.f;
    float4 o[8];
    #pragma unroll
    for (int k=0;k<8;k++) o[k] = make_float4(0.f,0.f,0.f,0.f);
    const float scale = 0.17677669529663687f;  // 1/sqrt(32)

    for (int j=0;j<256;j++){
        float s = 0.f;
        #pragma unroll
        for (int k=0;k<8;k++){
            float4 kv = Ks[j*9+k];
            s += q[k].x*kv.x + q[k].y*kv.y + q[k].z*kv.z + q[k].w*kv.w;
        }
        int dj = j>>6, hj = (j>>3)&7, wj = j&7;
        int rel = (di-dj+3)*225 + (hi-hj+7)*15 + (wi-wj+7);
        s = s*scale + btab[rel];
        if (shifted && sreg[j]!=myreg) s -= 1e9f;

        float p;
        if (s <= m){
            p = __expf(s - m);
        } else {
            float corr = __expf(m - s);
            l *= corr;
            #pragma unroll
            for (int k=0;k<8;k++){
                o[k].x*=corr; o[k].y*=corr; o[k].z*=corr; o[k].w*=corr;
            }
            m = s; p = 1.f;
        }
        l += p;
        #pragma unroll
        for (int k=0;k<8;k++){
            float4 vv = Vs[j*9+k];
            o[k].x += p*vv.x; o[k].y += p*vv.y; o[k].z += p*vv.z; o[k].w += p*vv.w;
        }
    }

    float inv = 1.f/l;
    float4* op = (float4*)(att + (size_t)tok*CDIM + head*32);
    #pragma unroll
    for (int k=0;k<8;k++){
        float4 vv = o[k];
        vv.x*=inv; vv.y*=inv; vv.z*=inv; vv.w*=inv;
        op[k] = vv;
    }
}

// ---------------- final transpose (B,D,Hp,Wp,C) -> (B,C,D,Hp,Wp) ----------------
__global__ void to_out_kernel(const float* __restrict__ y, float* __restrict__ out)
{
    int t = blockIdx.x, c = threadIdx.x;
    int wp = t % WPX, hp = (t/WPX) % HPX, d = (t/(WPX*HPX)) % DDIM, b = t/(WPX*HPX*DDIM);
    out[ (((size_t)(b*CDIM + c)*DDIM + d)*HPX + hp)*WPX + wp ] = y[(size_t)t*CDIM + c];
}

// ---------------- launch ----------------
#define ATT_SMEM 81152   // 2*256*9*16 + 1575*4 + 256*4 = 81052, rounded

extern "C" void kernel_launch(void* const* d_in, const int* in_sizes, int n_in,
                              void* d_out, int out_size)
{
    const float* x      = (const float*)d_in[0];
    const float* conv_w = (const float*)d_in[1];
    const float* conv_b = (const float*)d_in[2];
    const float* ln1_s  = (const float*)d_in[3];
    const float* ln1_b  = (const float*)d_in[4];
    const float* qkv_w  = (const float*)d_in[5];   // (L, 256, 768)
    const float* out_w  = (const float*)d_in[6];   // (L, 256, 256)
    const float* out_b  = (const float*)d_in[7];   // (L, 256)
    const float* bias_t = (const float*)d_in[8];   // (L, 1575, 8)
    const float* ln2_s  = (const float*)d_in[9];
    const float* ln2_b  = (const float*)d_in[10];
    const float* fc1_w  = (const float*)d_in[11];  // (L, 256, 1024)
    const float* fc1_b  = (const float*)d_in[12];  // (L, 1024)
    const float* fc2_w  = (const float*)d_in[13];  // (L, 1024, 256)
    const float* fc2_b  = (const float*)d_in[14];  // (L, 256)
    float* out = (float*)d_out;

    cudaFuncSetAttribute(attn_kernel, cudaFuncAttributeMaxDynamicSharedMemorySize, ATT_SMEM);

    float *gy, *gxn, *gqkv, *gatt, *gh;
    cudaGetSymbolAddress((void**)&gy,   g_y);
    cudaGetSymbolAddress((void**)&gxn,  g_xn);
    cudaGetSymbolAddress((void**)&gqkv, g_qkv);
    cudaGetSymbolAddress((void**)&gatt, g_att);
    cudaGetSymbolAddress((void**)&gh,   g_h);

    patch_embed_kernel<<<NTOK, 256>>>(x, conv_w, conv_b, gy);

    for (int L=0; L<4; L++){
        int shifted = L & 1;
        ln_kernel<<<NTOK, 256>>>(gy, gxn, ln1_s + L*256, ln1_b + L*256);
        sgemm_kernel<0><<<dim3(6, 392), 256>>>(gxn, qkv_w + (size_t)L*256*768, nullptr, gqkv, 768, 256);
        attn_kernel<<<dim3(BATCH*NWIN, 8), 256, ATT_SMEM>>>(gqkv, bias_t + (size_t)L*NBIAS*8, gatt, shifted);
        sgemm_kernel<2><<<dim3(2, 392), 256>>>(gatt, out_w + (size_t)L*256*256, out_b + L*256, gy, 256, 256);
        ln_kernel<<<NTOK, 256>>>(gy, gxn, ln2_s + L*256, ln2_b + L*256);
        sgemm_kernel<1><<<dim3(8, 392), 256>>>(gxn, fc1_w + (size_t)L*256*1024, fc1_b + L*1024, gh, 1024, 256);
        sgemm_kernel<2><<<dim3(2, 392), 256>>>(gh, fc2_w + (size_t)L*1024*256, fc2_b + L*256, gy, 256, 1024);
    }

    to_out_kernel<<<NTOK, 256>>>(gy, out);
}

// round 7
// speedup vs baseline: 1.5082x; 1.5082x over previous
#include <cuda_runtime.h>
#include <cuda_bf16.h>
#include <cstdint>

// ---------------- problem constants ----------------
#define BATCH 2
#define DDIM  8
#define HPX   56
#define WPX   56
#define CDIM  256
#define NTOK  (BATCH*DDIM*HPX*WPX)   // 50176
#define NWIN  98
#define NBIAS 1575
#define MLPD  1024

// ---------------- scratch ----------------
__device__ float g_y  [NTOK*CDIM];        // residual stream, fp32
__device__ float g_qkv[NTOK*3*CDIM];      // qkv projections fp32
__device__ __nv_bfloat16 g_ah[NTOK*CDIM]; // activation hi (K<=256 inputs)
__device__ __nv_bfloat16 g_al[NTOK*CDIM];
__device__ __nv_bfloat16 g_bh[NTOK*MLPD]; // gelu out hi (fc2 input)
__device__ __nv_bfloat16 g_bl[NTOK*MLPD];
// transposed + split weights: [M_out, K] K-major
__device__ __nv_bfloat16 w_qkv_h[4*768*256],  w_qkv_l[4*768*256];
__device__ __nv_bfloat16 w_out_h[4*256*256],  w_out_l[4*256*256];
__device__ __nv_bfloat16 w_fc1_h[4*1024*256], w_fc1_l[4*1024*256];
__device__ __nv_bfloat16 w_fc2_h[4*256*1024], w_fc2_l[4*256*1024];

// ---------------- helpers ----------------
__device__ __forceinline__ uint32_t smem_u32(const void* p){
    uint32_t a;
    asm("{ .reg .u64 t; cvta.to.shared.u64 t, %1; cvt.u32.u64 %0, t; }" : "=r"(a) : "l"(p));
    return a;
}
__device__ __forceinline__ void cp16(uint32_t dst, const void* src){
    asm volatile("cp.async.cg.shared.global [%0], [%1], 16;" :: "r"(dst), "l"(src));
}
__device__ __forceinline__ void cp_commit(){
    asm volatile("cp.async.commit_group;" ::: "memory");
}
template<int N>
__device__ __forceinline__ void cp_wait(){
    asm volatile("cp.async.wait_group %0;" :: "n"(N) : "memory");
}
__device__ __forceinline__ void ldsm4(uint32_t addr, uint32_t* r){
    asm volatile("ldmatrix.sync.aligned.m8n8.x4.shared.b16 {%0,%1,%2,%3}, [%4];"
        : "=r"(r[0]), "=r"(r[1]), "=r"(r[2]), "=r"(r[3]) : "r"(addr));
}
__device__ __forceinline__ void mma16816(float* c, const uint32_t* a, uint32_t b0, uint32_t b1){
    asm volatile("mma.sync.aligned.m16n8k16.row.col.f32.bf16.bf16.f32 "
        "{%0,%1,%2,%3}, {%4,%5,%6,%7}, {%8,%9}, {%0,%1,%2,%3};"
        : "+f"(c[0]), "+f"(c[1]), "+f"(c[2]), "+f"(c[3])
        : "r"(a[0]), "r"(a[1]), "r"(a[2]), "r"(a[3]), "r"(b0), "r"(b1));
}
__device__ __forceinline__ void split2(float x, __nv_bfloat16& h, __nv_bfloat16& l){
    h = __float2bfloat16_rn(x);
    l = __float2bfloat16_rn(x - __bfloat162float(h));
}
__device__ __forceinline__ float gelu_tanh(float x){
    float x3 = x*x*x;
    return 0.5f*x*(1.f + tanhf(0.7978845608028654f*(x + 0.044715f*x3)));
}

// ---------------- weight prep: W[K,M] fp32 -> Wt[M,K] bf16 hi/lo ----------------
__global__ void wprep_kernel(const float* __restrict__ W, __nv_bfloat16* __restrict__ oh,
                             __nv_bfloat16* __restrict__ ol, int K, int M)
{
    int ly = blockIdx.y;
    size_t n = (size_t)K*M;
    const float* w = W + ly*n;
    __nv_bfloat16* h = oh + ly*n;
    __nv_bfloat16* l = ol + ly*n;
    for (size_t i = (size_t)blockIdx.x*blockDim.x + threadIdx.x; i < n; i += (size_t)gridDim.x*blockDim.x){
        int k = (int)(i / M), m = (int)(i % M);
        float v = w[i];
        __nv_bfloat16 hh, ll;
        split2(v, hh, ll);
        h[(size_t)m*K + k] = hh;
        l[(size_t)m*K + k] = ll;
    }
}

// ---------------- patch embed ----------------
__global__ void patch_embed_kernel(const float* __restrict__ x,
                                   const float* __restrict__ w,
                                   const float* __restrict__ b,
                                   float* __restrict__ y)
{
    int t = blockIdx.x;
    int wp = t % WPX, hp = (t/WPX) % HPX, d = (t/(WPX*HPX)) % DDIM, bb = t/(WPX*HPX*DDIM);
    __shared__ float patch[64];
    int tid = threadIdx.x;
    if (tid < 64){
        int ic = tid>>4, kh = (tid>>2)&3, kw = tid&3;
        patch[tid] = x[ (((size_t)(bb*4+ic)*DDIM + d)*224 + hp*4+kh)*224 + wp*4+kw ];
    }
    __syncthreads();
    float acc = b[tid];
    const float* wr = w + tid*64;
    #pragma unroll
    for (int k=0;k<64;k++) acc += patch[k]*wr[k];
    y[(size_t)t*CDIM + tid] = acc;
}

// ---------------- layernorm -> bf16 hi/lo ----------------
__global__ void ln_kernel(const float* __restrict__ in,
                          __nv_bfloat16* __restrict__ oh, __nv_bfloat16* __restrict__ ol,
                          const float* __restrict__ sc, const float* __restrict__ bi)
{
    int t = blockIdx.x, c = threadIdx.x;
    float v = in[(size_t)t*CDIM + c];
    float s1 = v, s2 = v*v;
    #pragma unroll
    for (int o=16;o;o>>=1){
        s1 += __shfl_xor_sync(0xffffffffu, s1, o);
        s2 += __shfl_xor_sync(0xffffffffu, s2, o);
    }
    __shared__ float r1[8], r2[8];
    if ((c&31)==0){ r1[c>>5]=s1; r2[c>>5]=s2; }
    __syncthreads();
    s1 = 0.f; s2 = 0.f;
    #pragma unroll
    for (int k=0;k<8;k++){ s1 += r1[k]; s2 += r2[k]; }
    float mean = s1*(1.f/256.f);
    float var  = s2*(1.f/256.f) - mean*mean;
    float rs = rsqrtf(var + 1e-5f);
    float r = (v-mean)*rs*sc[c] + bi[c];
    __nv_bfloat16 hh, ll;
    split2(r, hh, ll);
    oh[(size_t)t*CDIM + c] = hh;
    ol[(size_t)t*CDIM + c] = ll;
}

// ---------------- HMMA split-bf16 GEMM ----------------
// A (act): [NTOK, K] bf16 hi/lo K-major.  B (weight): [M, K] bf16 hi/lo K-major.
// CTA: 128 rows x 128 cols, 512 threads = 16 warps (4 m x 4 n), warp tile 32x32.
// K chunks of 64, double-buffered cp.async.
// Smem per buffer: Ah | Al | Bh | Bl, each 128x64 bf16 = 16KB, XOR-swizzled.
// MODE 0: fp32 out, no bias. MODE 2: bias + residual accumulate (fp32 in/out).
// MODE 3: bias + gelu -> bf16 hi/lo out.
#define MG_BUF   65536
#define MG_TOTAL 131072

template<int MODE>
__global__ void __launch_bounds__(512, 1)
mgemm_kernel(const __nv_bfloat16* __restrict__ Ah, const __nv_bfloat16* __restrict__ Al,
             const __nv_bfloat16* __restrict__ Bh, const __nv_bfloat16* __restrict__ Bl,
             const float* __restrict__ bias, float* __restrict__ C,
             __nv_bfloat16* __restrict__ Oh, __nv_bfloat16* __restrict__ Ol,
             int M, int K)
{
    extern __shared__ char smem[];
    uint32_t sb = smem_u32(smem);
    int tid = threadIdx.x, lane = tid & 31, wid = tid >> 5;
    int wm = wid & 3, wn = wid >> 2;          // 4x4 warp grid
    int row0 = blockIdx.y*128, col0 = blockIdx.x*128;

    const __nv_bfloat16* gAh = Ah + (size_t)row0*K;
    const __nv_bfloat16* gAl = Al + (size_t)row0*K;
    const __nv_bfloat16* gBh = Bh + (size_t)col0*K;
    const __nv_bfloat16* gBl = Bl + (size_t)col0*K;

    float acc[2][4][4];
    #pragma unroll
    for (int i=0;i<2;i++)
        #pragma unroll
        for (int j=0;j<4;j++)
            #pragma unroll
            for (int k=0;k<4;k++) acc[i][j][k]=0.f;

    // per-lane ldmatrix address components: row = r0 + (lane&15), chunk += lane>>4
    int lrow = lane & 15, lch = lane >> 4;

    int nchunk = K >> 6;

    // ---- prologue: load chunk 0 into buf 0 ----
    {
        int k0 = 0;
        uint32_t bb = sb;
        #pragma unroll
        for (int h=0; h<2; h++){
            int i = tid + (h<<9);
            int r = i>>3, ch = i&7;
            uint32_t doff = (r<<7) + ((ch ^ (r&7))<<4);
            size_t soff = (size_t)r*K + k0 + (ch<<3);
            cp16(bb +         doff, gAh + soff);
            cp16(bb + 16384 + doff, gAl + soff);
            cp16(bb + 32768 + doff, gBh + soff);
            cp16(bb + 49152 + doff, gBl + soff);
        }
        cp_commit();
    }

    #pragma unroll 1
    for (int c = 0; c < nchunk; c++){
        if (c+1 < nchunk){
            int k0 = (c+1) << 6;
            uint32_t bb = sb + ((c+1)&1)*MG_BUF;
            #pragma unroll
            for (int h=0; h<2; h++){
                int i = tid + (h<<9);
                int r = i>>3, ch = i&7;
                uint32_t doff = (r<<7) + ((ch ^ (r&7))<<4);
                size_t soff = (size_t)r*K + k0 + (ch<<3);
                cp16(bb +         doff, gAh + soff);
                cp16(bb + 16384 + doff, gAl + soff);
                cp16(bb + 32768 + doff, gBh + soff);
                cp16(bb + 49152 + doff, gBl + soff);
            }
            cp_commit();
            cp_wait<1>();
        } else {
            cp_wait<0>();
        }
        __syncthreads();

        uint32_t tb = sb + (c&1)*MG_BUF;
        uint32_t tAh = tb, tAl = tb + 16384, tBh = tb + 32768, tBl = tb + 49152;

        #pragma unroll
        for (int ks = 0; ks < 4; ks++){
            int ch0 = ks*2 + lch;
            uint32_t a_h[2][4], a_l[2][4], b_h[2][4], b_l[2][4];
            #pragma unroll
            for (int mt=0; mt<2; mt++){
                int row = wm*32 + mt*16 + lrow;
                uint32_t off = (row<<7) + ((ch0 ^ (row&7))<<4);
                ldsm4(tAh + off, a_h[mt]);
                ldsm4(tAl + off, a_l[mt]);
            }
            #pragma unroll
            for (int np=0; np<2; np++){
                int row = wn*32 + np*16 + lrow;
                uint32_t off = (row<<7) + ((ch0 ^ (row&7))<<4);
                ldsm4(tBh + off, b_h[np]);
                ldsm4(tBl + off, b_l[np]);
            }
            #pragma unroll
            for (int mt=0; mt<2; mt++){
                #pragma unroll
                for (int nt=0; nt<4; nt++){
                    int np = nt>>1, hf = nt&1;
                    uint32_t bh0 = b_h[np][hf], bh1 = b_h[np][hf+2];
                    uint32_t bl0 = b_l[np][hf], bl1 = b_l[np][hf+2];
                    mma16816(acc[mt][nt], a_h[mt], bh0, bh1);
                    mma16816(acc[mt][nt], a_h[mt], bl0, bl1);
                    mma16816(acc[mt][nt], a_l[mt], bh0, bh1);
                }
            }
        }
        __syncthreads();
    }

    // ---- epilogue ----
    int lr = lane >> 2, lc = (lane & 3) * 2;
    #pragma unroll
    for (int mt=0; mt<2; mt++){
        #pragma unroll
        for (int nt=0; nt<4; nt++){
            int col = col0 + wn*32 + nt*8 + lc;
            #pragma unroll
            for (int half=0; half<2; half++){
                int row = row0 + wm*32 + mt*16 + lr + half*8;
                float v0 = acc[mt][nt][half*2+0];
                float v1 = acc[mt][nt][half*2+1];
                if (MODE == 0){
                    float2 r; r.x = v0; r.y = v1;
                    *(float2*)(C + (size_t)row*M + col) = r;
                } else if (MODE == 2){
                    float2* cp = (float2*)(C + (size_t)row*M + col);
                    float2 o = *cp;
                    float2 r;
                    r.x = v0 + bias[col+0] + o.x;
                    r.y = v1 + bias[col+1] + o.y;
                    *cp = r;
                } else {
                    float a = gelu_tanh(v0 + bias[col+0]);
                    float b = gelu_tanh(v1 + bias[col+1]);
                    __nv_bfloat16 ha, la, hb, lb;
                    split2(a, ha, la);
                    split2(b, hb, lb);
                    __nv_bfloat162 h2; h2.x = ha; h2.y = hb;
                    __nv_bfloat162 l2; l2.x = la; l2.y = lb;
                    *(__nv_bfloat162*)(Oh + (size_t)row*M + col) = h2;
                    *(__nv_bfloat162*)(Ol + (size_t)row*M + col) = l2;
                }
            }
        }
    }
}

// ---------------- fused window attention (fp32, outputs bf16 hi/lo) ----------------
__global__ void attn_kernel(const float* __restrict__ qkv,
                            const float* __restrict__ btab_g,
                            __nv_bfloat16* __restrict__ outh,
                            __nv_bfloat16* __restrict__ outl, int shifted)
{
    extern __shared__ float4 sm[];
    float4* Ks = sm;
    float4* Vs = sm + 256*9;
    float*  btab = (float*)(Vs + 256*9);
    int*    sreg = (int*)(btab + NBIAS);

    int head = blockIdx.y;
    int bw = blockIdx.x;
    int b = bw / NWIN, w = bw % NWIN;
    int wd = w/49, wh = (w/7)%7, ww = w%7;
    int i = threadIdx.x;
    int di = i>>6, hi = (i>>3)&7, wi = i&7;
    int dr = wd*4+di, hr = wh*8+hi, wr = ww*8+wi;

    int rd = dr<4?0:(dr<6?1:2);
    int rh = hr<48?0:(hr<52?1:2);
    int rw = wr<48?0:(wr<52?1:2);
    int myreg = rd*9 + rh*3 + rw;
    sreg[i] = myreg;

    int d = dr, h = hr, w2 = wr;
    if (shifted){ d = (dr+2)&7; h = (hr+4)%HPX; w2 = (wr+4)%WPX; }
    int tok = ((b*DDIM + d)*HPX + h)*WPX + w2;

    const float4* base = (const float4*)(qkv + (size_t)tok*768 + head*32);
    float4 q[8];
    #pragma unroll
    for (int k=0;k<8;k++){
        q[k]      = base[k];
        Ks[i*9+k] = base[64+k];
        Vs[i*9+k] = base[128+k];
    }
    for (int t=i; t<NBIAS; t+=256) btab[t] = btab_g[t*8 + head];
    __syncthreads();

    float m = -1e30f, l = 0.f;
    float4 o[8];
    #pragma unroll
    for (int k=0;k<8;k++) o[k] = make_float4(0.f,0.f,0.f,0.f);
    const float scale = 0.17677669529663687f;

    for (int j=0;j<256;j++){
        float s = 0.f;
        #pragma unroll
        for (int k=0;k<8;k++){
            float4 kv = Ks[j*9+k];
            s += q[k].x*kv.x + q[k].y*kv.y + q[k].z*kv.z + q[k].w*kv.w;
        }
        int dj = j>>6, hj = (j>>3)&7, wj = j&7;
        int rel = (di-dj+3)*225 + (hi-hj+7)*15 + (wi-wj+7);
        s = s*scale + btab[rel];
        if (shifted && sreg[j]!=myreg) s -= 1e9f;

        float p;
        if (s <= m){
            p = __expf(s - m);
        } else {
            float corr = __expf(m - s);
            l *= corr;
            #pragma unroll
            for (int k=0;k<8;k++){
                o[k].x*=corr; o[k].y*=corr; o[k].z*=corr; o[k].w*=corr;
            }
            m = s; p = 1.f;
        }
        l += p;
        #pragma unroll
        for (int k=0;k<8;k++){
            float4 vv = Vs[j*9+k];
            o[k].x += p*vv.x; o[k].y += p*vv.y; o[k].z += p*vv.z; o[k].w += p*vv.w;
        }
    }

    float inv = 1.f/l;
    __nv_bfloat162* hp = (__nv_bfloat162*)(outh + (size_t)tok*CDIM + head*32);
    __nv_bfloat162* lp = (__nv_bfloat162*)(outl + (size_t)tok*CDIM + head*32);
    #pragma unroll
    for (int k=0;k<8;k++){
        float4 vv = o[k];
        __nv_bfloat16 h0,l0,h1,l1,h2,l2,h3,l3;
        split2(vv.x*inv, h0, l0);
        split2(vv.y*inv, h1, l1);
        split2(vv.z*inv, h2, l2);
        split2(vv.w*inv, h3, l3);
        __nv_bfloat162 ha; ha.x=h0; ha.y=h1;
        __nv_bfloat162 hb; hb.x=h2; hb.y=h3;
        __nv_bfloat162 la; la.x=l0; la.y=l1;
        __nv_bfloat162 lb; lb.x=l2; lb.y=l3;
        hp[k*2+0]=ha; hp[k*2+1]=hb;
        lp[k*2+0]=la; lp[k*2+1]=lb;
    }
}

// ---------------- final transpose ----------------
__global__ void to_out_kernel(const float* __restrict__ y, float* __restrict__ out)
{
    int t = blockIdx.x, c = threadIdx.x;
    int wp = t % WPX, hp = (t/WPX) % HPX, d = (t/(WPX*HPX)) % DDIM, b = t/(WPX*HPX*DDIM);
    out[ (((size_t)(b*CDIM + c)*DDIM + d)*HPX + hp)*WPX + wp ] = y[(size_t)t*CDIM + c];
}

// ---------------- launch ----------------
#define ATT_SMEM 81152

extern "C" void kernel_launch(void* const* d_in, const int* in_sizes, int n_in,
                              void* d_out, int out_size)
{
    const float* x      = (const float*)d_in[0];
    const float* conv_w = (const float*)d_in[1];
    const float* conv_b = (const float*)d_in[2];
    const float* ln1_s  = (const float*)d_in[3];
    const float* ln1_b  = (const float*)d_in[4];
    const float* qkv_w  = (const float*)d_in[5];
    const float* out_w  = (const float*)d_in[6];
    const float* out_b  = (const float*)d_in[7];
    const float* bias_t = (const float*)d_in[8];
    const float* ln2_s  = (const float*)d_in[9];
    const float* ln2_b  = (const float*)d_in[10];
    const float* fc1_w  = (const float*)d_in[11];
    const float* fc1_b  = (const float*)d_in[12];
    const float* fc2_w  = (const float*)d_in[13];
    const float* fc2_b  = (const float*)d_in[14];
    float* out = (float*)d_out;

    cudaFuncSetAttribute(attn_kernel, cudaFuncAttributeMaxDynamicSharedMemorySize, ATT_SMEM);
    cudaFuncSetAttribute(mgemm_kernel<0>, cudaFuncAttributeMaxDynamicSharedMemorySize, MG_TOTAL);
    cudaFuncSetAttribute(mgemm_kernel<2>, cudaFuncAttributeMaxDynamicSharedMemorySize, MG_TOTAL);
    cudaFuncSetAttribute(mgemm_kernel<3>, cudaFuncAttributeMaxDynamicSharedMemorySize, MG_TOTAL);

    float *gy, *gqkv;
    __nv_bfloat16 *gah, *gal, *gbh, *gbl;
    __nv_bfloat16 *wqh, *wql, *woh, *wol, *w1h, *w1l, *w2h, *w2l;
    cudaGetSymbolAddress((void**)&gy,   g_y);
    cudaGetSymbolAddress((void**)&gqkv, g_qkv);
    cudaGetSymbolAddress((void**)&gah,  g_ah);
    cudaGetSymbolAddress((void**)&gal,  g_al);
    cudaGetSymbolAddress((void**)&gbh,  g_bh);
    cudaGetSymbolAddress((void**)&gbl,  g_bl);
    cudaGetSymbolAddress((void**)&wqh,  w_qkv_h);
    cudaGetSymbolAddress((void**)&wql,  w_qkv_l);
    cudaGetSymbolAddress((void**)&woh,  w_out_h);
    cudaGetSymbolAddress((void**)&wol,  w_out_l);
    cudaGetSymbolAddress((void**)&w1h,  w_fc1_h);
    cudaGetSymbolAddress((void**)&w1l,  w_fc1_l);
    cudaGetSymbolAddress((void**)&w2h,  w_fc2_h);
    cudaGetSymbolAddress((void**)&w2l,  w_fc2_l);

    // weight transpose + split
    wprep_kernel<<<dim3(512,4), 256>>>(qkv_w, wqh, wql, 256, 768);
    wprep_kernel<<<dim3(512,4), 256>>>(out_w, woh, wol, 256, 256);
    wprep_kernel<<<dim3(512,4), 256>>>(fc1_w, w1h, w1l, 256, 1024);
    wprep_kernel<<<dim3(512,4), 256>>>(fc2_w, w2h, w2l, 1024, 256);

    patch_embed_kernel<<<NTOK, 256>>>(x, conv_w, conv_b, gy);

    for (int L=0; L<4; L++){
        int shifted = L & 1;
        ln_kernel<<<NTOK, 256>>>(gy, gah, gal, ln1_s + L*256, ln1_b + L*256);
        mgemm_kernel<0><<<dim3(6, 392), 512, MG_TOTAL>>>(gah, gal,
            wqh + (size_t)L*768*256, wql + (size_t)L*768*256,
            nullptr, gqkv, nullptr, nullptr, 768, 256);
        attn_kernel<<<dim3(BATCH*NWIN, 8), 256, ATT_SMEM>>>(gqkv, bias_t + (size_t)L*NBIAS*8, gah, gal, shifted);
        mgemm_kernel<2><<<dim3(2, 392), 512, MG_TOTAL>>>(gah, gal,
            woh + (size_t)L*256*256, wol + (size_t)L*256*256,
            out_b + L*256, gy, nullptr, nullptr, 256, 256);
        ln_kernel<<<NTOK, 256>>>(gy, gah, gal, ln2_s + L*256, ln2_b + L*256);
        mgemm_kernel<3><<<dim3(8, 392), 512, MG_TOTAL>>>(gah, gal,
            w1h + (size_t)L*1024*256, w1l + (size_t)L*1024*256,
            fc1_b + L*1024, nullptr, gbh, gbl, 1024, 256);
        mgemm_kernel<2><<<dim3(2, 392), 512, MG_TOTAL>>>(gbh, gbl,
            w2h + (size_t)L*256*1024, w2l + (size_t)L*256*1024,
            fc2_b + L*256, gy, nullptr, nullptr, 256, 1024);
    }

    to_out_kernel<<<NTOK, 256>>>(gy, out);
}

// round 8
// speedup vs baseline: 1.7048x; 1.1303x over previous
#include <cuda_runtime.h>
#include <cuda_bf16.h>
#include <cstdint>

// ---------------- problem constants ----------------
#define BATCH 2
#define DDIM  8
#define HPX   56
#define WPX   56
#define CDIM  256
#define NTOK  (BATCH*DDIM*HPX*WPX)   // 50176
#define NSPAT (DDIM*HPX*WPX)         // 25088
#define NWIN  98
#define NBIAS 1575
#define MLPD  1024

// ---------------- scratch ----------------
__device__ float g_y  [NTOK*CDIM];        // residual stream, fp32
__device__ float g_qkv[NTOK*3*CDIM];      // qkv projections fp32
__device__ __nv_bfloat16 g_ah[NTOK*CDIM]; // activation hi
__device__ __nv_bfloat16 g_al[NTOK*CDIM];
__device__ __nv_bfloat16 g_bh[NTOK*MLPD]; // gelu out hi (fc2 input)
__device__ __nv_bfloat16 g_bl[NTOK*MLPD];
// transposed + split weights: [M_out, K] K-major
__device__ __nv_bfloat16 w_qkv_h[4*768*256],  w_qkv_l[4*768*256];
__device__ __nv_bfloat16 w_out_h[4*256*256],  w_out_l[4*256*256];
__device__ __nv_bfloat16 w_fc1_h[4*1024*256], w_fc1_l[4*1024*256];
__device__ __nv_bfloat16 w_fc2_h[4*256*1024], w_fc2_l[4*256*1024];

// ---------------- helpers ----------------
__device__ __forceinline__ uint32_t smem_u32(const void* p){
    uint32_t a;
    asm("{ .reg .u64 t; cvta.to.shared.u64 t, %1; cvt.u32.u64 %0, t; }" : "=r"(a) : "l"(p));
    return a;
}
__device__ __forceinline__ void cp16(uint32_t dst, const void* src){
    asm volatile("cp.async.cg.shared.global [%0], [%1], 16;" :: "r"(dst), "l"(src));
}
__device__ __forceinline__ void cp_commit(){
    asm volatile("cp.async.commit_group;" ::: "memory");
}
template<int N>
__device__ __forceinline__ void cp_wait(){
    asm volatile("cp.async.wait_group %0;" :: "n"(N) : "memory");
}
__device__ __forceinline__ void ldsm4(uint32_t addr, uint32_t* r){
    asm volatile("ldmatrix.sync.aligned.m8n8.x4.shared.b16 {%0,%1,%2,%3}, [%4];"
        : "=r"(r[0]), "=r"(r[1]), "=r"(r[2]), "=r"(r[3]) : "r"(addr));
}
__device__ __forceinline__ void mma16816(float* c, const uint32_t* a, uint32_t b0, uint32_t b1){
    asm volatile("mma.sync.aligned.m16n8k16.row.col.f32.bf16.bf16.f32 "
        "{%0,%1,%2,%3}, {%4,%5,%6,%7}, {%8,%9}, {%0,%1,%2,%3};"
        : "+f"(c[0]), "+f"(c[1]), "+f"(c[2]), "+f"(c[3])
        : "r"(a[0]), "r"(a[1]), "r"(a[2]), "r"(a[3]), "r"(b0), "r"(b1));
}
// packed f32x2 (Blackwell): halves FFMA issue count
__device__ __forceinline__ unsigned long long ffma2(unsigned long long a, unsigned long long b, unsigned long long c){
    unsigned long long d;
    asm("fma.rn.f32x2 %0, %1, %2, %3;" : "=l"(d) : "l"(a), "l"(b), "l"(c));
    return d;
}
__device__ __forceinline__ unsigned long long fmul2(unsigned long long a, unsigned long long b){
    unsigned long long d;
    asm("mul.rn.f32x2 %0, %1, %2;" : "=l"(d) : "l"(a), "l"(b));
    return d;
}
__device__ __forceinline__ unsigned long long pack2(float x, float y){
    unsigned long long d;
    asm("mov.b64 %0, {%1, %2};" : "=l"(d) : "f"(x), "f"(y));
    return d;
}
__device__ __forceinline__ void unpack2(unsigned long long v, float& x, float& y){
    asm("mov.b64 {%0, %1}, %2;" : "=f"(x), "=f"(y) : "l"(v));
}
__device__ __forceinline__ void split2(float x, __nv_bfloat16& h, __nv_bfloat16& l){
    h = __float2bfloat16_rn(x);
    l = __float2bfloat16_rn(x - __bfloat162float(h));
}
__device__ __forceinline__ float gelu_tanh(float x){
    float x3 = x*x*x;
    return 0.5f*x*(1.f + tanhf(0.7978845608028654f*(x + 0.044715f*x3)));
}

// ---------------- weight prep: W[K,M] fp32 -> Wt[M,K] bf16 hi/lo ----------------
__global__ void wprep_kernel(const float* __restrict__ W, __nv_bfloat16* __restrict__ oh,
                             __nv_bfloat16* __restrict__ ol, int K, int M)
{
    int ly = blockIdx.y;
    size_t n = (size_t)K*M;
    const float* w = W + ly*n;
    __nv_bfloat16* h = oh + ly*n;
    __nv_bfloat16* l = ol + ly*n;
    for (size_t i = (size_t)blockIdx.x*blockDim.x + threadIdx.x; i < n; i += (size_t)gridDim.x*blockDim.x){
        int k = (int)(i / M), m = (int)(i % M);
        float v = w[i];
        __nv_bfloat16 hh, ll;
        split2(v, hh, ll);
        h[(size_t)m*K + k] = hh;
        l[(size_t)m*K + k] = ll;
    }
}

// ---------------- patch embed ----------------
__global__ void patch_embed_kernel(const float* __restrict__ x,
                                   const float* __restrict__ w,
                                   const float* __restrict__ b,
                                   float* __restrict__ y)
{
    int t = blockIdx.x;
    int wp = t % WPX, hp = (t/WPX) % HPX, d = (t/(WPX*HPX)) % DDIM, bb = t/(WPX*HPX*DDIM);
    __shared__ float patch[64];
    int tid = threadIdx.x;
    if (tid < 64){
        int ic = tid>>4, kh = (tid>>2)&3, kw = tid&3;
        patch[tid] = x[ (((size_t)(bb*4+ic)*DDIM + d)*224 + hp*4+kh)*224 + wp*4+kw ];
    }
    __syncthreads();
    float acc = b[tid];
    const float* wr = w + tid*64;
    #pragma unroll
    for (int k=0;k<64;k++) acc += patch[k]*wr[k];
    y[(size_t)t*CDIM + tid] = acc;
}

// ---------------- layernorm: warp per token, 8 tokens/block ----------------
__global__ void ln_kernel(const float* __restrict__ in,
                          __nv_bfloat16* __restrict__ oh, __nv_bfloat16* __restrict__ ol,
                          const float* __restrict__ sc, const float* __restrict__ bi)
{
    int warp = threadIdx.x >> 5, lane = threadIdx.x & 31;
    int t = blockIdx.x*8 + warp;
    const float4* row = (const float4*)(in + (size_t)t*CDIM);
    float4 a = row[lane*2], b = row[lane*2+1];
    float s1 = a.x+a.y+a.z+a.w + b.x+b.y+b.z+b.w;
    float s2 = a.x*a.x+a.y*a.y+a.z*a.z+a.w*a.w + b.x*b.x+b.y*b.y+b.z*b.z+b.w*b.w;
    #pragma unroll
    for (int o=16;o;o>>=1){
        s1 += __shfl_xor_sync(0xffffffffu, s1, o);
        s2 += __shfl_xor_sync(0xffffffffu, s2, o);
    }
    float mean = s1*(1.f/256.f);
    float var  = s2*(1.f/256.f) - mean*mean;
    float rs = rsqrtf(var + 1e-5f);
    int c0 = lane*8;
    float4 sca = *(const float4*)(sc + c0), scb = *(const float4*)(sc + c0 + 4);
    float4 bia = *(const float4*)(bi + c0), bib = *(const float4*)(bi + c0 + 4);
    float r[8];
    r[0]=(a.x-mean)*rs*sca.x+bia.x; r[1]=(a.y-mean)*rs*sca.y+bia.y;
    r[2]=(a.z-mean)*rs*sca.z+bia.z; r[3]=(a.w-mean)*rs*sca.w+bia.w;
    r[4]=(b.x-mean)*rs*scb.x+bib.x; r[5]=(b.y-mean)*rs*scb.y+bib.y;
    r[6]=(b.z-mean)*rs*scb.z+bib.z; r[7]=(b.w-mean)*rs*scb.w+bib.w;
    __nv_bfloat162 hh[4], ll[4];
    #pragma unroll
    for (int i=0;i<4;i++){
        __nv_bfloat16 h0,l0,h1,l1;
        split2(r[i*2+0], h0, l0);
        split2(r[i*2+1], h1, l1);
        hh[i].x=h0; hh[i].y=h1;
        ll[i].x=l0; ll[i].y=l1;
    }
    *(uint4*)(oh + (size_t)t*CDIM + c0) = *(uint4*)hh;
    *(uint4*)(ol + (size_t)t*CDIM + c0) = *(uint4*)ll;
}

// ---------------- HMMA split-bf16 GEMM ----------------
// CTA: 128 rows x 64 cols, 256 threads = 8 warps (4m x 2n), warp tile 32x32.
// K chunks of 64, double-buffered cp.async; stage = Ah16K|Al16K|Bh8K|Bl8K = 48KB, 2 stages = 96KB -> 2 CTA/SM.
#define MG_STAGE 49152
#define MG_TOTAL 98304

template<int MODE>
__global__ void __launch_bounds__(256, 2)
mgemm_kernel(const __nv_bfloat16* __restrict__ Ah, const __nv_bfloat16* __restrict__ Al,
             const __nv_bfloat16* __restrict__ Bh, const __nv_bfloat16* __restrict__ Bl,
             const float* __restrict__ bias, float* __restrict__ C,
             __nv_bfloat16* __restrict__ Oh, __nv_bfloat16* __restrict__ Ol,
             int M, int K)
{
    extern __shared__ char smem[];
    uint32_t sb = smem_u32(smem);
    int tid = threadIdx.x, lane = tid & 31, wid = tid >> 5;
    int wm = wid & 3, wn = wid >> 2;          // 4 x 2 warp grid
    int row0 = blockIdx.y*128, col0 = blockIdx.x*64;

    const __nv_bfloat16* gAh = Ah + (size_t)row0*K;
    const __nv_bfloat16* gAl = Al + (size_t)row0*K;
    const __nv_bfloat16* gBh = Bh + (size_t)col0*K;
    const __nv_bfloat16* gBl = Bl + (size_t)col0*K;

    float acc[2][4][4];
    #pragma unroll
    for (int i=0;i<2;i++)
        #pragma unroll
        for (int j=0;j<4;j++)
            #pragma unroll
            for (int k=0;k<4;k++) acc[i][j][k]=0.f;

    int lrow = lane & 15, lch = lane >> 4;
    int nchunk = K >> 6;

    // prologue: chunk 0 -> stage 0
    {
        uint32_t bb = sb;
        #pragma unroll
        for (int h=0; h<4; h++){
            int i = tid + (h<<8);
            int r = i>>3, ch = i&7;
            uint32_t doff = (r<<7) + ((ch ^ (r&7))<<4);
            size_t soff = (size_t)r*K + (ch<<3);
            cp16(bb +         doff, gAh + soff);
            cp16(bb + 16384 + doff, gAl + soff);
        }
        #pragma unroll
        for (int h=0; h<2; h++){
            int i = tid + (h<<8);
            int r = i>>3, ch = i&7;
            uint32_t doff = (r<<7) + ((ch ^ (r&7))<<4);
            size_t soff = (size_t)r*K + (ch<<3);
            cp16(bb + 32768 + doff, gBh + soff);
            cp16(bb + 40960 + doff, gBl + soff);
        }
        cp_commit();
    }

    #pragma unroll 1
    for (int c = 0; c < nchunk; c++){
        if (c+1 < nchunk){
            int k0 = (c+1) << 6;
            uint32_t bb = sb + ((c+1)&1)*MG_STAGE;
            #pragma unroll
            for (int h=0; h<4; h++){
                int i = tid + (h<<8);
                int r = i>>3, ch = i&7;
                uint32_t doff = (r<<7) + ((ch ^ (r&7))<<4);
                size_t soff = (size_t)r*K + k0 + (ch<<3);
                cp16(bb +         doff, gAh + soff);
                cp16(bb + 16384 + doff, gAl + soff);
            }
            #pragma unroll
            for (int h=0; h<2; h++){
                int i = tid + (h<<8);
                int r = i>>3, ch = i&7;
                uint32_t doff = (r<<7) + ((ch ^ (r&7))<<4);
                size_t soff = (size_t)r*K + k0 + (ch<<3);
                cp16(bb + 32768 + doff, gBh + soff);
                cp16(bb + 40960 + doff, gBl + soff);
            }
            cp_commit();
            cp_wait<1>();
        } else {
            cp_wait<0>();
        }
        __syncthreads();

        uint32_t tb = sb + (c&1)*MG_STAGE;
        uint32_t tAh = tb, tAl = tb + 16384, tBh = tb + 32768, tBl = tb + 40960;

        #pragma unroll
        for (int ks = 0; ks < 4; ks++){
            int ch0 = ks*2 + lch;
            uint32_t a_h[2][4], a_l[2][4], b_h[2][4], b_l[2][4];
            #pragma unroll
            for (int mt=0; mt<2; mt++){
                int row = wm*32 + mt*16 + lrow;
                uint32_t off = (row<<7) + ((ch0 ^ (row&7))<<4);
                ldsm4(tAh + off, a_h[mt]);
                ldsm4(tAl + off, a_l[mt]);
            }
            #pragma unroll
            for (int np=0; np<2; np++){
                int row = wn*32 + np*16 + lrow;
                uint32_t off = (row<<7) + ((ch0 ^ (row&7))<<4);
                ldsm4(tBh + off, b_h[np]);
                ldsm4(tBl + off, b_l[np]);
            }
            #pragma unroll
            for (int mt=0; mt<2; mt++){
                #pragma unroll
                for (int nt=0; nt<4; nt++){
                    int np = nt>>1, hf = nt&1;
                    uint32_t bh0 = b_h[np][hf], bh1 = b_h[np][hf+2];
                    uint32_t bl0 = b_l[np][hf], bl1 = b_l[np][hf+2];
                    mma16816(acc[mt][nt], a_h[mt], bh0, bh1);
                    mma16816(acc[mt][nt], a_h[mt], bl0, bl1);
                    mma16816(acc[mt][nt], a_l[mt], bh0, bh1);
                }
            }
        }
        __syncthreads();
    }

    // ---- epilogue ----
    int lr = lane >> 2, lc = (lane & 3) * 2;
    #pragma unroll
    for (int mt=0; mt<2; mt++){
        #pragma unroll
        for (int nt=0; nt<4; nt++){
            int col = col0 + wn*32 + nt*8 + lc;
            #pragma unroll
            for (int half=0; half<2; half++){
                int row = row0 + wm*32 + mt*16 + lr + half*8;
                float v0 = acc[mt][nt][half*2+0];
                float v1 = acc[mt][nt][half*2+1];
                if (MODE == 0){
                    float2 r; r.x = v0; r.y = v1;
                    *(float2*)(C + (size_t)row*M + col) = r;
                } else if (MODE == 2){
                    float2* cp = (float2*)(C + (size_t)row*M + col);
                    float2 o = *cp;
                    float2 r;
                    r.x = v0 + bias[col+0] + o.x;
                    r.y = v1 + bias[col+1] + o.y;
                    *cp = r;
                } else {
                    float a = gelu_tanh(v0 + bias[col+0]);
                    float b = gelu_tanh(v1 + bias[col+1]);
                    __nv_bfloat16 ha, la, hb, lb;
                    split2(a, ha, la);
                    split2(b, hb, lb);
                    __nv_bfloat162 h2; h2.x = ha; h2.y = hb;
                    __nv_bfloat162 l2; l2.x = la; l2.y = lb;
                    *(__nv_bfloat162*)(Oh + (size_t)row*M + col) = h2;
                    *(__nv_bfloat162*)(Ol + (size_t)row*M + col) = l2;
                }
            }
        }
    }
}

// ---------------- fused window attention (f32x2 packed math) ----------------
__global__ void attn_kernel(const float* __restrict__ qkv,
                            const float* __restrict__ btab_g,
                            __nv_bfloat16* __restrict__ outh,
                            __nv_bfloat16* __restrict__ outl, int shifted)
{
    extern __shared__ float4 sm[];
    float4* Ks = sm;
    float4* Vs = sm + 256*9;
    float*  btab = (float*)(Vs + 256*9);
    int*    sreg = (int*)(btab + NBIAS);

    int head = blockIdx.y;
    int bw = blockIdx.x;
    int b = bw / NWIN, w = bw % NWIN;
    int wd = w/49, wh = (w/7)%7, ww = w%7;
    int i = threadIdx.x;
    int di = i>>6, hi = (i>>3)&7, wi = i&7;
    int dr = wd*4+di, hr = wh*8+hi, wr = ww*8+wi;

    int rd = dr<4?0:(dr<6?1:2);
    int rh = hr<48?0:(hr<52?1:2);
    int rw = wr<48?0:(wr<52?1:2);
    int myreg = rd*9 + rh*3 + rw;
    sreg[i] = myreg;

    int d = dr, h = hr, w2 = wr;
    if (shifted){ d = (dr+2)&7; h = (hr+4)%HPX; w2 = (wr+4)%WPX; }
    int tok = ((b*DDIM + d)*HPX + h)*WPX + w2;

    const float4* base = (const float4*)(qkv + (size_t)tok*768 + head*32);
    unsigned long long q2[16];
    #pragma unroll
    for (int k=0;k<8;k++){
        float4 qv = base[k];
        q2[2*k+0] = pack2(qv.x, qv.y);
        q2[2*k+1] = pack2(qv.z, qv.w);
        Ks[i*9+k] = base[64+k];
        Vs[i*9+k] = base[128+k];
    }
    for (int t=i; t<NBIAS; t+=256) btab[t] = btab_g[t*8 + head];
    __syncthreads();

    float m = -1e30f, l = 0.f;
    unsigned long long o2[16];
    const unsigned long long z2 = 0ull;
    #pragma unroll
    for (int k=0;k<16;k++) o2[k] = z2;
    const float scale = 0.17677669529663687f;

    for (int j=0;j<256;j++){
        const ulonglong2* Kj = (const ulonglong2*)&Ks[j*9];
        unsigned long long accA = z2, accB = z2;
        #pragma unroll
        for (int k=0;k<8;k++){
            ulonglong2 kv = Kj[k];
            accA = ffma2(q2[2*k+0], kv.x, accA);
            accB = ffma2(q2[2*k+1], kv.y, accB);
        }
        float ax, ay, bx, by;
        unpack2(accA, ax, ay);
        unpack2(accB, bx, by);
        float s = (ax+ay) + (bx+by);

        int dj = j>>6, hj = (j>>3)&7, wj = j&7;
        int rel = (di-dj+3)*225 + (hi-hj+7)*15 + (wi-wj+7);
        s = s*scale + btab[rel];
        if (shifted && sreg[j]!=myreg) s -= 1e9f;

        float p;
        if (s <= m){
            p = __expf(s - m);
        } else {
            float corr = __expf(m - s);
            unsigned long long c2 = pack2(corr, corr);
            l *= corr;
            #pragma unroll
            for (int k=0;k<16;k++) o2[k] = fmul2(c2, o2[k]);
            m = s; p = 1.f;
        }
        l += p;
        unsigned long long p2 = pack2(p, p);
        const ulonglong2* Vj = (const ulonglong2*)&Vs[j*9];
        #pragma unroll
        for (int k=0;k<8;k++){
            ulonglong2 vv = Vj[k];
            o2[2*k+0] = ffma2(p2, vv.x, o2[2*k+0]);
            o2[2*k+1] = ffma2(p2, vv.y, o2[2*k+1]);
        }
    }

    float inv = 1.f/l;
    __nv_bfloat162* hp = (__nv_bfloat162*)(outh + (size_t)tok*CDIM + head*32);
    __nv_bfloat162* lp = (__nv_bfloat162*)(outl + (size_t)tok*CDIM + head*32);
    #pragma unroll
    for (int k=0;k<16;k++){
        float x, y;
        unpack2(o2[k], x, y);
        __nv_bfloat16 h0,l0,h1,l1;
        split2(x*inv, h0, l0);
        split2(y*inv, h1, l1);
        __nv_bfloat162 hv; hv.x=h0; hv.y=h1;
        __nv_bfloat162 lv; lv.x=l0; lv.y=l1;
        hp[k]=hv; lp[k]=lv;
    }
}

// ---------------- final transpose: tiled, coalesced ----------------
__global__ void to_out_kernel(const float* __restrict__ y, float* __restrict__ out)
{
    __shared__ float tile[32][33];
    int b = blockIdx.z;
    int c0 = blockIdx.y*32, s0 = blockIdx.x*32;
    int tx = threadIdx.x & 31, ty = threadIdx.x >> 5;
    #pragma unroll
    for (int i=0;i<4;i++)
        tile[ty + i*8][tx] = y[((size_t)b*NSPAT + s0 + ty + i*8)*CDIM + c0 + tx];
    __syncthreads();
    #pragma unroll
    for (int i=0;i<4;i++)
        out[((size_t)(b*CDIM + c0 + ty + i*8))*NSPAT + s0 + tx] = tile[tx][ty + i*8];
}

// ---------------- launch ----------------
#define ATT_SMEM 81152

extern "C" void kernel_launch(void* const* d_in, const int* in_sizes, int n_in,
                              void* d_out, int out_size)
{
    const float* x      = (const float*)d_in[0];
    const float* conv_w = (const float*)d_in[1];
    const float* conv_b = (const float*)d_in[2];
    const float* ln1_s  = (const float*)d_in[3];
    const float* ln1_b  = (const float*)d_in[4];
    const float* qkv_w  = (const float*)d_in[5];
    const float* out_w  = (const float*)d_in[6];
    const float* out_b  = (const float*)d_in[7];
    const float* bias_t = (const float*)d_in[8];
    const float* ln2_s  = (const float*)d_in[9];
    const float* ln2_b  = (const float*)d_in[10];
    const float* fc1_w  = (const float*)d_in[11];
    const float* fc1_b  = (const float*)d_in[12];
    const float* fc2_w  = (const float*)d_in[13];
    const float* fc2_b  = (const float*)d_in[14];
    float* out = (float*)d_out;

    cudaFuncSetAttribute(attn_kernel, cudaFuncAttributeMaxDynamicSharedMemorySize, ATT_SMEM);
    cudaFuncSetAttribute(mgemm_kernel<0>, cudaFuncAttributeMaxDynamicSharedMemorySize, MG_TOTAL);
    cudaFuncSetAttribute(mgemm_kernel<2>, cudaFuncAttributeMaxDynamicSharedMemorySize, MG_TOTAL);
    cudaFuncSetAttribute(mgemm_kernel<3>, cudaFuncAttributeMaxDynamicSharedMemorySize, MG_TOTAL);

    float *gy, *gqkv;
    __nv_bfloat16 *gah, *gal, *gbh, *gbl;
    __nv_bfloat16 *wqh, *wql, *woh, *wol, *w1h, *w1l, *w2h, *w2l;
    cudaGetSymbolAddress((void**)&gy,   g_y);
    cudaGetSymbolAddress((void**)&gqkv, g_qkv);
    cudaGetSymbolAddress((void**)&gah,  g_ah);
    cudaGetSymbolAddress((void**)&gal,  g_al);
    cudaGetSymbolAddress((void**)&gbh,  g_bh);
    cudaGetSymbolAddress((void**)&gbl,  g_bl);
    cudaGetSymbolAddress((void**)&wqh,  w_qkv_h);
    cudaGetSymbolAddress((void**)&wql,  w_qkv_l);
    cudaGetSymbolAddress((void**)&woh,  w_out_h);
    cudaGetSymbolAddress((void**)&wol,  w_out_l);
    cudaGetSymbolAddress((void**)&w1h,  w_fc1_h);
    cudaGetSymbolAddress((void**)&w1l,  w_fc1_l);
    cudaGetSymbolAddress((void**)&w2h,  w_fc2_h);
    cudaGetSymbolAddress((void**)&w2l,  w_fc2_l);

    // weight transpose + split
    wprep_kernel<<<dim3(512,4), 256>>>(qkv_w, wqh, wql, 256, 768);
    wprep_kernel<<<dim3(512,4), 256>>>(out_w, woh, wol, 256, 256);
    wprep_kernel<<<dim3(512,4), 256>>>(fc1_w, w1h, w1l, 256, 1024);
    wprep_kernel<<<dim3(512,4), 256>>>(fc2_w, w2h, w2l, 1024, 256);

    patch_embed_kernel<<<NTOK, 256>>>(x, conv_w, conv_b, gy);

    for (int L=0; L<4; L++){
        int shifted = L & 1;
        ln_kernel<<<NTOK/8, 256>>>(gy, gah, gal, ln1_s + L*256, ln1_b + L*256);
        mgemm_kernel<0><<<dim3(12, 392), 256, MG_TOTAL>>>(gah, gal,
            wqh + (size_t)L*768*256, wql + (size_t)L*768*256,
            nullptr, gqkv, nullptr, nullptr, 768, 256);
        attn_kernel<<<dim3(BATCH*NWIN, 8), 256, ATT_SMEM>>>(gqkv, bias_t + (size_t)L*NBIAS*8, gah, gal, shifted);
        mgemm_kernel<2><<<dim3(4, 392), 256, MG_TOTAL>>>(gah, gal,
            woh + (size_t)L*256*256, wol + (size_t)L*256*256,
            out_b + L*256, gy, nullptr, nullptr, 256, 256);
        ln_kernel<<<NTOK/8, 256>>>(gy, gah, gal, ln2_s + L*256, ln2_b + L*256);
        mgemm_kernel<3><<<dim3(16, 392), 256, MG_TOTAL>>>(gah, gal,
            w1h + (size_t)L*1024*256, w1l + (size_t)L*1024*256,
            fc1_b + L*1024, nullptr, gbh, gbl, 1024, 256);
        mgemm_kernel<2><<<dim3(4, 392), 256, MG_TOTAL>>>(gbh, gbl,
            w2h + (size_t)L*256*1024, w2l + (size_t)L*256*1024,
            fc2_b + L*256, gy, nullptr, nullptr, 256, 1024);
    }

    to_out_kernel<<<dim3(NSPAT/32, CDIM/32, BATCH), 256>>>(gy, out);
}

// round 9
// speedup vs baseline: 1.8476x; 1.0838x over previous
#include <cuda_runtime.h>
#include <cuda_fp16.h>
#include <cstdint>

// ---------------- problem constants ----------------
#define BATCH 2
#define DDIM  8
#define HPX   56
#define WPX   56
#define CDIM  256
#define NTOK  (BATCH*DDIM*HPX*WPX)   // 50176
#define NSPAT (DDIM*HPX*WPX)         // 25088
#define NWIN  98
#define NBIAS 1575
#define MLPD  1024

// ---------------- scratch ----------------
__device__ float g_y  [NTOK*CDIM];        // residual stream, fp32
__device__ float g_qkv[NTOK*3*CDIM];      // qkv projections fp32
__device__ __half g_ah[NTOK*CDIM];        // activation hi (fp16 split)
__device__ __half g_al[NTOK*CDIM];
__device__ __half g_bh[NTOK*MLPD];        // gelu out hi (fc2 input)
__device__ __half g_bl[NTOK*MLPD];
// transposed fp16 weights: [M_out, K] K-major (single term)
__device__ __half w_qkv[4*768*256];
__device__ __half w_out[4*256*256];
__device__ __half w_fc1[4*1024*256];
__device__ __half w_fc2[4*256*1024];

// ---------------- helpers ----------------
__device__ __forceinline__ uint32_t smem_u32(const void* p){
    uint32_t a;
    asm("{ .reg .u64 t; cvta.to.shared.u64 t, %1; cvt.u32.u64 %0, t; }" : "=r"(a) : "l"(p));
    return a;
}
__device__ __forceinline__ void cp16(uint32_t dst, const void* src){
    asm volatile("cp.async.cg.shared.global [%0], [%1], 16;" :: "r"(dst), "l"(src));
}
__device__ __forceinline__ void cp_commit(){
    asm volatile("cp.async.commit_group;" ::: "memory");
}
template<int N>
__device__ __forceinline__ void cp_wait(){
    asm volatile("cp.async.wait_group %0;" :: "n"(N) : "memory");
}
__device__ __forceinline__ void ldsm4(uint32_t addr, uint32_t* r){
    asm volatile("ldmatrix.sync.aligned.m8n8.x4.shared.b16 {%0,%1,%2,%3}, [%4];"
        : "=r"(r[0]), "=r"(r[1]), "=r"(r[2]), "=r"(r[3]) : "r"(addr));
}
__device__ __forceinline__ void mma16816h(float* c, const uint32_t* a, uint32_t b0, uint32_t b1){
    asm volatile("mma.sync.aligned.m16n8k16.row.col.f32.f16.f16.f32 "
        "{%0,%1,%2,%3}, {%4,%5,%6,%7}, {%8,%9}, {%0,%1,%2,%3};"
        : "+f"(c[0]), "+f"(c[1]), "+f"(c[2]), "+f"(c[3])
        : "r"(a[0]), "r"(a[1]), "r"(a[2]), "r"(a[3]), "r"(b0), "r"(b1));
}
// packed f32x2 (Blackwell)
__device__ __forceinline__ unsigned long long ffma2(unsigned long long a, unsigned long long b, unsigned long long c){
    unsigned long long d;
    asm("fma.rn.f32x2 %0, %1, %2, %3;" : "=l"(d) : "l"(a), "l"(b), "l"(c));
    return d;
}
__device__ __forceinline__ unsigned long long fmul2(unsigned long long a, unsigned long long b){
    unsigned long long d;
    asm("mul.rn.f32x2 %0, %1, %2;" : "=l"(d) : "l"(a), "l"(b));
    return d;
}
__device__ __forceinline__ unsigned long long pack2(float x, float y){
    unsigned long long d;
    asm("mov.b64 %0, {%1, %2};" : "=l"(d) : "f"(x), "f"(y));
    return d;
}
__device__ __forceinline__ void unpack2(unsigned long long v, float& x, float& y){
    asm("mov.b64 {%0, %1}, %2;" : "=f"(x), "=f"(y) : "l"(v));
}
__device__ __forceinline__ void split2h(float x, __half& h, __half& l){
    h = __float2half_rn(x);
    l = __float2half_rn(x - __half2float(h));
}
__device__ __forceinline__ float gelu_tanh(float x){
    float x3 = x*x*x;
    return 0.5f*x*(1.f + tanhf(0.7978845608028654f*(x + 0.044715f*x3)));
}

// ---------------- weight prep: W[K,M] fp32 -> Wt[M,K] fp16 ----------------
__global__ void wprep_kernel(const float* __restrict__ W, __half* __restrict__ oh,
                             int K, int M)
{
    int ly = blockIdx.y;
    size_t n = (size_t)K*M;
    const float* w = W + ly*n;
    __half* h = oh + ly*n;
    for (size_t i = (size_t)blockIdx.x*blockDim.x + threadIdx.x; i < n; i += (size_t)gridDim.x*blockDim.x){
        int k = (int)(i / M), m = (int)(i % M);
        h[(size_t)m*K + k] = __float2half_rn(w[i]);
    }
}

// ---------------- patch embed ----------------
__global__ void patch_embed_kernel(const float* __restrict__ x,
                                   const float* __restrict__ w,
                                   const float* __restrict__ b,
                                   float* __restrict__ y)
{
    int t = blockIdx.x;
    int wp = t % WPX, hp = (t/WPX) % HPX, d = (t/(WPX*HPX)) % DDIM, bb = t/(WPX*HPX*DDIM);
    __shared__ float patch[64];
    int tid = threadIdx.x;
    if (tid < 64){
        int ic = tid>>4, kh = (tid>>2)&3, kw = tid&3;
        patch[tid] = x[ (((size_t)(bb*4+ic)*DDIM + d)*224 + hp*4+kh)*224 + wp*4+kw ];
    }
    __syncthreads();
    float acc = b[tid];
    const float* wr = w + tid*64;
    #pragma unroll
    for (int k=0;k<64;k++) acc += patch[k]*wr[k];
    y[(size_t)t*CDIM + tid] = acc;
}

// ---------------- layernorm: warp per token, 8 tokens/block ----------------
__global__ void ln_kernel(const float* __restrict__ in,
                          __half* __restrict__ oh, __half* __restrict__ ol,
                          const float* __restrict__ sc, const float* __restrict__ bi)
{
    int warp = threadIdx.x >> 5, lane = threadIdx.x & 31;
    int t = blockIdx.x*8 + warp;
    const float4* row = (const float4*)(in + (size_t)t*CDIM);
    float4 a = row[lane*2], b = row[lane*2+1];
    float s1 = a.x+a.y+a.z+a.w + b.x+b.y+b.z+b.w;
    float s2 = a.x*a.x+a.y*a.y+a.z*a.z+a.w*a.w + b.x*b.x+b.y*b.y+b.z*b.z+b.w*b.w;
    #pragma unroll
    for (int o=16;o;o>>=1){
        s1 += __shfl_xor_sync(0xffffffffu, s1, o);
        s2 += __shfl_xor_sync(0xffffffffu, s2, o);
    }
    float mean = s1*(1.f/256.f);
    float var  = s2*(1.f/256.f) - mean*mean;
    float rs = rsqrtf(var + 1e-5f);
    int c0 = lane*8;
    float4 sca = *(const float4*)(sc + c0), scb = *(const float4*)(sc + c0 + 4);
    float4 bia = *(const float4*)(bi + c0), bib = *(const float4*)(bi + c0 + 4);
    float r[8];
    r[0]=(a.x-mean)*rs*sca.x+bia.x; r[1]=(a.y-mean)*rs*sca.y+bia.y;
    r[2]=(a.z-mean)*rs*sca.z+bia.z; r[3]=(a.w-mean)*rs*sca.w+bia.w;
    r[4]=(b.x-mean)*rs*scb.x+bib.x; r[5]=(b.y-mean)*rs*scb.y+bib.y;
    r[6]=(b.z-mean)*rs*scb.z+bib.z; r[7]=(b.w-mean)*rs*scb.w+bib.w;
    __half2 hh[4], ll[4];
    #pragma unroll
    for (int i=0;i<4;i++){
        __half h0,l0,h1,l1;
        split2h(r[i*2+0], h0, l0);
        split2h(r[i*2+1], h1, l1);
        hh[i] = __halves2half2(h0, h1);
        ll[i] = __halves2half2(l0, l1);
    }
    *(uint4*)(oh + (size_t)t*CDIM + c0) = *(uint4*)hh;
    *(uint4*)(ol + (size_t)t*CDIM + c0) = *(uint4*)ll;
}

// ---------------- HMMA fp16 2-term GEMM ----------------
// A (act): [NTOK, K] fp16 hi/lo K-major.  B (weight): [M, K] fp16 K-major.
// CTA: 128 rows x 64 cols, 256 threads = 8 warps (4m x 2n), warp tile 32x32.
// K chunks of 64, double-buffered cp.async; stage = Ah16K|Al16K|B8K = 40KB, 2 stages = 80KB -> 2 CTA/SM.
#define MG_STAGE 40960
#define MG_TOTAL 81920

template<int MODE>
__global__ void __launch_bounds__(256, 2)
mgemm_kernel(const __half* __restrict__ Ah, const __half* __restrict__ Al,
             const __half* __restrict__ B,
             const float* __restrict__ bias, float* __restrict__ C,
             __half* __restrict__ Oh, __half* __restrict__ Ol,
             int M, int K)
{
    extern __shared__ char smem[];
    uint32_t sb = smem_u32(smem);
    int tid = threadIdx.x, lane = tid & 31, wid = tid >> 5;
    int wm = wid & 3, wn = wid >> 2;          // 4 x 2 warp grid
    int row0 = blockIdx.y*128, col0 = blockIdx.x*64;

    const __half* gAh = Ah + (size_t)row0*K;
    const __half* gAl = Al + (size_t)row0*K;
    const __half* gB  = B  + (size_t)col0*K;

    float acc[2][4][4];
    #pragma unroll
    for (int i=0;i<2;i++)
        #pragma unroll
        for (int j=0;j<4;j++)
            #pragma unroll
            for (int k=0;k<4;k++) acc[i][j][k]=0.f;

    int lrow = lane & 15, lch = lane >> 4;
    int nchunk = K >> 6;

    // prologue: chunk 0 -> stage 0
    {
        uint32_t bb = sb;
        #pragma unroll
        for (int h=0; h<4; h++){
            int i = tid + (h<<8);
            int r = i>>3, ch = i&7;
            uint32_t doff = (r<<7) + ((ch ^ (r&7))<<4);
            size_t soff = (size_t)r*K + (ch<<3);
            cp16(bb +         doff, gAh + soff);
            cp16(bb + 16384 + doff, gAl + soff);
        }
        #pragma unroll
        for (int h=0; h<2; h++){
            int i = tid + (h<<8);
            int r = i>>3, ch = i&7;
            uint32_t doff = (r<<7) + ((ch ^ (r&7))<<4);
            size_t soff = (size_t)r*K + (ch<<3);
            cp16(bb + 32768 + doff, gB + soff);
        }
        cp_commit();
    }

    #pragma unroll 1
    for (int c = 0; c < nchunk; c++){
        if (c+1 < nchunk){
            int k0 = (c+1) << 6;
            uint32_t bb = sb + ((c+1)&1)*MG_STAGE;
            #pragma unroll
            for (int h=0; h<4; h++){
                int i = tid + (h<<8);
                int r = i>>3, ch = i&7;
                uint32_t doff = (r<<7) + ((ch ^ (r&7))<<4);
                size_t soff = (size_t)r*K + k0 + (ch<<3);
                cp16(bb +         doff, gAh + soff);
                cp16(bb + 16384 + doff, gAl + soff);
            }
            #pragma unroll
            for (int h=0; h<2; h++){
                int i = tid + (h<<8);
                int r = i>>3, ch = i&7;
                uint32_t doff = (r<<7) + ((ch ^ (r&7))<<4);
                size_t soff = (size_t)r*K + k0 + (ch<<3);
                cp16(bb + 32768 + doff, gB + soff);
            }
            cp_commit();
            cp_wait<1>();
        } else {
            cp_wait<0>();
        }
        __syncthreads();

        uint32_t tb = sb + (c&1)*MG_STAGE;
        uint32_t tAh = tb, tAl = tb + 16384, tB = tb + 32768;

        #pragma unroll
        for (int ks = 0; ks < 4; ks++){
            int ch0 = ks*2 + lch;
            uint32_t a_h[2][4], a_l[2][4], b_f[2][4];
            #pragma unroll
            for (int mt=0; mt<2; mt++){
                int row = wm*32 + mt*16 + lrow;
                uint32_t off = (row<<7) + ((ch0 ^ (row&7))<<4);
                ldsm4(tAh + off, a_h[mt]);
                ldsm4(tAl + off, a_l[mt]);
            }
            #pragma unroll
            for (int np=0; np<2; np++){
                int row = wn*32 + np*16 + lrow;
                uint32_t off = (row<<7) + ((ch0 ^ (row&7))<<4);
                ldsm4(tB + off, b_f[np]);
            }
            #pragma unroll
            for (int mt=0; mt<2; mt++){
                #pragma unroll
                for (int nt=0; nt<4; nt++){
                    int np = nt>>1, hf = nt&1;
                    uint32_t b0 = b_f[np][hf], b1 = b_f[np][hf+2];
                    mma16816h(acc[mt][nt], a_h[mt], b0, b1);
                    mma16816h(acc[mt][nt], a_l[mt], b0, b1);
                }
            }
        }
        __syncthreads();
    }

    // ---- epilogue ----
    int lr = lane >> 2, lc = (lane & 3) * 2;
    #pragma unroll
    for (int mt=0; mt<2; mt++){
        #pragma unroll
        for (int nt=0; nt<4; nt++){
            int col = col0 + wn*32 + nt*8 + lc;
            #pragma unroll
            for (int half=0; half<2; half++){
                int row = row0 + wm*32 + mt*16 + lr + half*8;
                float v0 = acc[mt][nt][half*2+0];
                float v1 = acc[mt][nt][half*2+1];
                if (MODE == 0){
                    float2 r; r.x = v0; r.y = v1;
                    *(float2*)(C + (size_t)row*M + col) = r;
                } else if (MODE == 2){
                    float2* cp = (float2*)(C + (size_t)row*M + col);
                    float2 o = *cp;
                    float2 r;
                    r.x = v0 + bias[col+0] + o.x;
                    r.y = v1 + bias[col+1] + o.y;
                    *cp = r;
                } else {
                    float a = gelu_tanh(v0 + bias[col+0]);
                    float b = gelu_tanh(v1 + bias[col+1]);
                    __half ha, la, hb, lb;
                    split2h(a, ha, la);
                    split2h(b, hb, lb);
                    *(__half2*)(Oh + (size_t)row*M + col) = __halves2half2(ha, hb);
                    *(__half2*)(Ol + (size_t)row*M + col) = __halves2half2(la, lb);
                }
            }
        }
    }
}

// ---------------- fused window attention (f32x2 packed math) ----------------
__global__ void attn_kernel(const float* __restrict__ qkv,
                            const float* __restrict__ btab_g,
                            __half* __restrict__ outh,
                            __half* __restrict__ outl, int shifted)
{
    extern __shared__ float4 sm[];
    float4* Ks = sm;
    float4* Vs = sm + 256*9;
    float*  btab = (float*)(Vs + 256*9);
    int*    sreg = (int*)(btab + NBIAS);

    int head = blockIdx.y;
    int bw = blockIdx.x;
    int b = bw / NWIN, w = bw % NWIN;
    int wd = w/49, wh = (w/7)%7, ww = w%7;
    int i = threadIdx.x;
    int di = i>>6, hi = (i>>3)&7, wi = i&7;
    int dr = wd*4+di, hr = wh*8+hi, wr = ww*8+wi;

    int rd = dr<4?0:(dr<6?1:2);
    int rh = hr<48?0:(hr<52?1:2);
    int rw = wr<48?0:(wr<52?1:2);
    int myreg = rd*9 + rh*3 + rw;
    sreg[i] = myreg;

    int d = dr, h = hr, w2 = wr;
    if (shifted){ d = (dr+2)&7; h = (hr+4)%HPX; w2 = (wr+4)%WPX; }
    int tok = ((b*DDIM + d)*HPX + h)*WPX + w2;

    const float4* base = (const float4*)(qkv + (size_t)tok*768 + head*32);
    unsigned long long q2[16];
    #pragma unroll
    for (int k=0;k<8;k++){
        float4 qv = base[k];
        q2[2*k+0] = pack2(qv.x, qv.y);
        q2[2*k+1] = pack2(qv.z, qv.w);
        Ks[i*9+k] = base[64+k];
        Vs[i*9+k] = base[128+k];
    }
    for (int t=i; t<NBIAS; t+=256) btab[t] = btab_g[t*8 + head];
    __syncthreads();

    float m = -1e30f, l = 0.f;
    unsigned long long o2[16];
    const unsigned long long z2 = 0ull;
    #pragma unroll
    for (int k=0;k<16;k++) o2[k] = z2;
    const float scale = 0.17677669529663687f;

    for (int j=0;j<256;j++){
        const ulonglong2* Kj = (const ulonglong2*)&Ks[j*9];
        unsigned long long accA = z2, accB = z2;
        #pragma unroll
        for (int k=0;k<8;k++){
            ulonglong2 kv = Kj[k];
            accA = ffma2(q2[2*k+0], kv.x, accA);
            accB = ffma2(q2[2*k+1], kv.y, accB);
        }
        float ax, ay, bx, by;
        unpack2(accA, ax, ay);
        unpack2(accB, bx, by);
        float s = (ax+ay) + (bx+by);

        int dj = j>>6, hj = (j>>3)&7, wj = j&7;
        int rel = (di-dj+3)*225 + (hi-hj+7)*15 + (wi-wj+7);
        s = s*scale + btab[rel];
        if (shifted && sreg[j]!=myreg) s -= 1e9f;

        float p;
        if (s <= m){
            p = __expf(s - m);
        } else {
            float corr = __expf(m - s);
            unsigned long long c2 = pack2(corr, corr);
            l *= corr;
            #pragma unroll
            for (int k=0;k<16;k++) o2[k] = fmul2(c2, o2[k]);
            m = s; p = 1.f;
        }
        l += p;
        unsigned long long p2 = pack2(p, p);
        const ulonglong2* Vj = (const ulonglong2*)&Vs[j*9];
        #pragma unroll
        for (int k=0;k<8;k++){
            ulonglong2 vv = Vj[k];
            o2[2*k+0] = ffma2(p2, vv.x, o2[2*k+0]);
            o2[2*k+1] = ffma2(p2, vv.y, o2[2*k+1]);
        }
    }

    float inv = 1.f/l;
    __half2* hp = (__half2*)(outh + (size_t)tok*CDIM + head*32);
    __half2* lp = (__half2*)(outl + (size_t)tok*CDIM + head*32);
    #pragma unroll
    for (int k=0;k<16;k++){
        float x, y;
        unpack2(o2[k], x, y);
        __half h0,l0,h1,l1;
        split2h(x*inv, h0, l0);
        split2h(y*inv, h1, l1);
        hp[k] = __halves2half2(h0, h1);
        lp[k] = __halves2half2(l0, l1);
    }
}

// ---------------- final transpose: tiled, coalesced ----------------
__global__ void to_out_kernel(const float* __restrict__ y, float* __restrict__ out)
{
    __shared__ float tile[32][33];
    int b = blockIdx.z;
    int c0 = blockIdx.y*32, s0 = blockIdx.x*32;
    int tx = threadIdx.x & 31, ty = threadIdx.x >> 5;
    #pragma unroll
    for (int i=0;i<4;i++)
        tile[ty + i*8][tx] = y[((size_t)b*NSPAT + s0 + ty + i*8)*CDIM + c0 + tx];
    __syncthreads();
    #pragma unroll
    for (int i=0;i<4;i++)
        out[((size_t)(b*CDIM + c0 + ty + i*8))*NSPAT + s0 + tx] = tile[tx][ty + i*8];
}

// ---------------- launch ----------------
#define ATT_SMEM 81152

extern "C" void kernel_launch(void* const* d_in, const int* in_sizes, int n_in,
                              void* d_out, int out_size)
{
    const float* x      = (const float*)d_in[0];
    const float* conv_w = (const float*)d_in[1];
    const float* conv_b = (const float*)d_in[2];
    const float* ln1_s  = (const float*)d_in[3];
    const float* ln1_b  = (const float*)d_in[4];
    const float* qkv_w  = (const float*)d_in[5];
    const float* out_w  = (const float*)d_in[6];
    const float* out_b  = (const float*)d_in[7];
    const float* bias_t = (const float*)d_in[8];
    const float* ln2_s  = (const float*)d_in[9];
    const float* ln2_b  = (const float*)d_in[10];
    const float* fc1_w  = (const float*)d_in[11];
    const float* fc1_b  = (const float*)d_in[12];
    const float* fc2_w  = (const float*)d_in[13];
    const float* fc2_b  = (const float*)d_in[14];
    float* out = (float*)d_out;

    cudaFuncSetAttribute(attn_kernel, cudaFuncAttributeMaxDynamicSharedMemorySize, ATT_SMEM);
    cudaFuncSetAttribute(mgemm_kernel<0>, cudaFuncAttributeMaxDynamicSharedMemorySize, MG_TOTAL);
    cudaFuncSetAttribute(mgemm_kernel<2>, cudaFuncAttributeMaxDynamicSharedMemorySize, MG_TOTAL);
    cudaFuncSetAttribute(mgemm_kernel<3>, cudaFuncAttributeMaxDynamicSharedMemorySize, MG_TOTAL);

    float *gy, *gqkv;
    __half *gah, *gal, *gbh, *gbl;
    __half *wq, *wo, *w1, *w2;
    cudaGetSymbolAddress((void**)&gy,   g_y);
    cudaGetSymbolAddress((void**)&gqkv, g_qkv);
    cudaGetSymbolAddress((void**)&gah,  g_ah);
    cudaGetSymbolAddress((void**)&gal,  g_al);
    cudaGetSymbolAddress((void**)&gbh,  g_bh);
    cudaGetSymbolAddress((void**)&gbl,  g_bl);
    cudaGetSymbolAddress((void**)&wq,   w_qkv);
    cudaGetSymbolAddress((void**)&wo,   w_out);
    cudaGetSymbolAddress((void**)&w1,   w_fc1);
    cudaGetSymbolAddress((void**)&w2,   w_fc2);

    // weight transpose + fp16 round
    wprep_kernel<<<dim3(512,4), 256>>>(qkv_w, wq, 256, 768);
    wprep_kernel<<<dim3(512,4), 256>>>(out_w, wo, 256, 256);
    wprep_kernel<<<dim3(512,4), 256>>>(fc1_w, w1, 256, 1024);
    wprep_kernel<<<dim3(512,4), 256>>>(fc2_w, w2, 1024, 256);

    patch_embed_kernel<<<NTOK, 256>>>(x, conv_w, conv_b, gy);

    for (int L=0; L<4; L++){
        int shifted = L & 1;
        ln_kernel<<<NTOK/8, 256>>>(gy, gah, gal, ln1_s + L*256, ln1_b + L*256);
        mgemm_kernel<0><<<dim3(12, 392), 256, MG_TOTAL>>>(gah, gal,
            wq + (size_t)L*768*256,
            nullptr, gqkv, nullptr, nullptr, 768, 256);
        attn_kernel<<<dim3(BATCH*NWIN, 8), 256, ATT_SMEM>>>(gqkv, bias_t + (size_t)L*NBIAS*8, gah, gal, shifted);
        mgemm_kernel<2><<<dim3(4, 392), 256, MG_TOTAL>>>(gah, gal,
            wo + (size_t)L*256*256,
            out_b + L*256, gy, nullptr, nullptr, 256, 256);
        ln_kernel<<<NTOK/8, 256>>>(gy, gah, gal, ln2_s + L*256, ln2_b + L*256);
        mgemm_kernel<3><<<dim3(16, 392), 256, MG_TOTAL>>>(gah, gal,
            w1 + (size_t)L*1024*256,
            fc1_b + L*1024, nullptr, gbh, gbl, 1024, 256);
        mgemm_kernel<2><<<dim3(4, 392), 256, MG_TOTAL>>>(gbh, gbl,
            w2 + (size_t)L*256*1024,
            fc2_b + L*256, gy, nullptr, nullptr, 256, 1024);
    }

    to_out_kernel<<<dim3(NSPAT/32, CDIM/32, BATCH), 256>>>(gy, out);
}

// round 11
// speedup vs baseline: 2.3422x; 1.2677x over previous
#include <cuda_runtime.h>
#include <cuda_fp16.h>
#include <cstdint>

// ---------------- problem constants ----------------
#define BATCH 2
#define DDIM  8
#define HPX   56
#define WPX   56
#define CDIM  256
#define NTOK  (BATCH*DDIM*HPX*WPX)   // 50176
#define NSPAT (DDIM*HPX*WPX)         // 25088
#define NWIN  98
#define NBIAS 1575
#define MLPD  1024

// ---------------- scratch ----------------
__device__ float g_y  [NTOK*CDIM];        // residual stream, fp32
__device__ __half g_qkvh[NTOK*3*CDIM];    // qkv projections fp16
__device__ __half g_ah[NTOK*CDIM];        // activation hi (fp16 split)
__device__ __half g_al[NTOK*CDIM];
__device__ __half g_bh[NTOK*MLPD];        // gelu out hi (fc2 input)
__device__ __half g_bl[NTOK*MLPD];
// transposed fp16 weights: [M_out, K] K-major
__device__ __half w_qkv[4*768*256];
__device__ __half w_out[4*256*256];
__device__ __half w_fc1[4*1024*256];
__device__ __half w_fc2[4*256*1024];

// ---------------- helpers ----------------
__device__ __forceinline__ uint32_t smem_u32(const void* p){
    uint32_t a;
    asm("{ .reg .u64 t; cvta.to.shared.u64 t, %1; cvt.u32.u64 %0, t; }" : "=r"(a) : "l"(p));
    return a;
}
__device__ __forceinline__ void cp16(uint32_t dst, const void* src){
    asm volatile("cp.async.cg.shared.global [%0], [%1], 16;" :: "r"(dst), "l"(src));
}
__device__ __forceinline__ void cp_commit(){
    asm volatile("cp.async.commit_group;" ::: "memory");
}
template<int N>
__device__ __forceinline__ void cp_wait(){
    asm volatile("cp.async.wait_group %0;" :: "n"(N) : "memory");
}
__device__ __forceinline__ void ldsm4(uint32_t addr, uint32_t* r){
    asm volatile("ldmatrix.sync.aligned.m8n8.x4.shared.b16 {%0,%1,%2,%3}, [%4];"
        : "=r"(r[0]), "=r"(r[1]), "=r"(r[2]), "=r"(r[3]) : "r"(addr));
}
__device__ __forceinline__ void ldsm4t(uint32_t addr, uint32_t* r){
    asm volatile("ldmatrix.sync.aligned.m8n8.x4.trans.shared.b16 {%0,%1,%2,%3}, [%4];"
        : "=r"(r[0]), "=r"(r[1]), "=r"(r[2]), "=r"(r[3]) : "r"(addr));
}
__device__ __forceinline__ void mma16816h(float* c, const uint32_t* a, uint32_t b0, uint32_t b1){
    asm volatile("mma.sync.aligned.m16n8k16.row.col.f32.f16.f16.f32 "
        "{%0,%1,%2,%3}, {%4,%5,%6,%7}, {%8,%9}, {%0,%1,%2,%3};"
        : "+f"(c[0]), "+f"(c[1]), "+f"(c[2]), "+f"(c[3])
        : "r"(a[0]), "r"(a[1]), "r"(a[2]), "r"(a[3]), "r"(b0), "r"(b1));
}
__device__ __forceinline__ void split2h(float x, __half& h, __half& l){
    h = __float2half_rn(x);
    l = __float2half_rn(x - __half2float(h));
}
__device__ __forceinline__ float gelu_tanh(float x){
    float x3 = x*x*x;
    return 0.5f*x*(1.f + tanhf(0.7978845608028654f*(x + 0.044715f*x3)));
}

// ---------------- weight prep: W[K,M] fp32 -> Wt[M,K] fp16 ----------------
__global__ void wprep_kernel(const float* __restrict__ W, __half* __restrict__ oh,
                             int K, int M)
{
    int ly = blockIdx.y;
    size_t n = (size_t)K*M;
    const float* w = W + ly*n;
    __half* h = oh + ly*n;
    for (size_t i = (size_t)blockIdx.x*blockDim.x + threadIdx.x; i < n; i += (size_t)gridDim.x*blockDim.x){
        int k = (int)(i / M), m = (int)(i % M);
        h[(size_t)m*K + k] = __float2half_rn(w[i]);
    }
}

// ---------------- patch embed ----------------
__global__ void patch_embed_kernel(const float* __restrict__ x,
                                   const float* __restrict__ w,
                                   const float* __restrict__ b,
                                   float* __restrict__ y)
{
    int t = blockIdx.x;
    int wp = t % WPX, hp = (t/WPX) % HPX, d = (t/(WPX*HPX)) % DDIM, bb = t/(WPX*HPX*DDIM);
    __shared__ float patch[64];
    int tid = threadIdx.x;
    if (tid < 64){
        int ic = tid>>4, kh = (tid>>2)&3, kw = tid&3;
        patch[tid] = x[ (((size_t)(bb*4+ic)*DDIM + d)*224 + hp*4+kh)*224 + wp*4+kw ];
    }
    __syncthreads();
    float acc = b[tid];
    const float* wr = w + tid*64;
    #pragma unroll
    for (int k=0;k<64;k++) acc += patch[k]*wr[k];
    y[(size_t)t*CDIM + tid] = acc;
}

// ---------------- layernorm: warp per token, 8 tokens/block ----------------
__global__ void ln_kernel(const float* __restrict__ in,
                          __half* __restrict__ oh, __half* __restrict__ ol,
                          const float* __restrict__ sc, const float* __restrict__ bi)
{
    int warp = threadIdx.x >> 5, lane = threadIdx.x & 31;
    int t = blockIdx.x*8 + warp;
    const float4* row = (const float4*)(in + (size_t)t*CDIM);
    float4 a = row[lane*2], b = row[lane*2+1];
    float s1 = a.x+a.y+a.z+a.w + b.x+b.y+b.z+b.w;
    float s2 = a.x*a.x+a.y*a.y+a.z*a.z+a.w*a.w + b.x*b.x+b.y*b.y+b.z*b.z+b.w*b.w;
    #pragma unroll
    for (int o=16;o;o>>=1){
        s1 += __shfl_xor_sync(0xffffffffu, s1, o);
        s2 += __shfl_xor_sync(0xffffffffu, s2, o);
    }
    float mean = s1*(1.f/256.f);
    float var  = s2*(1.f/256.f) - mean*mean;
    float rs = rsqrtf(var + 1e-5f);
    int c0 = lane*8;
    float4 sca = *(const float4*)(sc + c0), scb = *(const float4*)(sc + c0 + 4);
    float4 bia = *(const float4*)(bi + c0), bib = *(const float4*)(bi + c0 + 4);
    float r[8];
    r[0]=(a.x-mean)*rs*sca.x+bia.x; r[1]=(a.y-mean)*rs*sca.y+bia.y;
    r[2]=(a.z-mean)*rs*sca.z+bia.z; r[3]=(a.w-mean)*rs*sca.w+bia.w;
    r[4]=(b.x-mean)*rs*scb.x+bib.x; r[5]=(b.y-mean)*rs*scb.y+bib.y;
    r[6]=(b.z-mean)*rs*scb.z+bib.z; r[7]=(b.w-mean)*rs*scb.w+bib.w;
    __half2 hh[4], ll[4];
    #pragma unroll
    for (int i=0;i<4;i++){
        __half h0,l0,h1,l1;
        split2h(r[i*2+0], h0, l0);
        split2h(r[i*2+1], h1, l1);
        hh[i] = __halves2half2(h0, h1);
        ll[i] = __halves2half2(l0, l1);
    }
    *(uint4*)(oh + (size_t)t*CDIM + c0) = *(uint4*)hh;
    *(uint4*)(ol + (size_t)t*CDIM + c0) = *(uint4*)ll;
}

// ---------------- HMMA fp16 2-term GEMM ----------------
// MODE 0: fp32 out. MODE 2: bias+residual fp32. MODE 3: bias+gelu -> fp16 hi/lo.
// MODE 4: fp16 out (no bias) — qkv path.
#define MG_STAGE 40960
#define MG_TOTAL 81920

template<int MODE>
__global__ void __launch_bounds__(256, 2)
mgemm_kernel(const __half* __restrict__ Ah, const __half* __restrict__ Al,
             const __half* __restrict__ B,
             const float* __restrict__ bias, float* __restrict__ C,
             __half* __restrict__ Oh, __half* __restrict__ Ol,
             int M, int K)
{
    extern __shared__ char smem[];
    uint32_t sb = smem_u32(smem);
    int tid = threadIdx.x, lane = tid & 31, wid = tid >> 5;
    int wm = wid & 3, wn = wid >> 2;
    int row0 = blockIdx.y*128, col0 = blockIdx.x*64;

    const __half* gAh = Ah + (size_t)row0*K;
    const __half* gAl = Al + (size_t)row0*K;
    const __half* gB  = B  + (size_t)col0*K;

    float acc[2][4][4];
    #pragma unroll
    for (int i=0;i<2;i++)
        #pragma unroll
        for (int j=0;j<4;j++)
            #pragma unroll
            for (int k=0;k<4;k++) acc[i][j][k]=0.f;

    int lrow = lane & 15, lch = lane >> 4;
    int nchunk = K >> 6;

    {
        uint32_t bb = sb;
        #pragma unroll
        for (int h=0; h<4; h++){
            int i = tid + (h<<8);
            int r = i>>3, ch = i&7;
            uint32_t doff = (r<<7) + ((ch ^ (r&7))<<4);
            size_t soff = (size_t)r*K + (ch<<3);
            cp16(bb +         doff, gAh + soff);
            cp16(bb + 16384 + doff, gAl + soff);
        }
        #pragma unroll
        for (int h=0; h<2; h++){
            int i = tid + (h<<8);
            int r = i>>3, ch = i&7;
            uint32_t doff = (r<<7) + ((ch ^ (r&7))<<4);
            size_t soff = (size_t)r*K + (ch<<3);
            cp16(bb + 32768 + doff, gB + soff);
        }
        cp_commit();
    }

    #pragma unroll 1
    for (int c = 0; c < nchunk; c++){
        if (c+1 < nchunk){
            int k0 = (c+1) << 6;
            uint32_t bb = sb + ((c+1)&1)*MG_STAGE;
            #pragma unroll
            for (int h=0; h<4; h++){
                int i = tid + (h<<8);
                int r = i>>3, ch = i&7;
                uint32_t doff = (r<<7) + ((ch ^ (r&7))<<4);
                size_t soff = (size_t)r*K + k0 + (ch<<3);
                cp16(bb +         doff, gAh + soff);
                cp16(bb + 16384 + doff, gAl + soff);
            }
            #pragma unroll
            for (int h=0; h<2; h++){
                int i = tid + (h<<8);
                int r = i>>3, ch = i&7;
                uint32_t doff = (r<<7) + ((ch ^ (r&7))<<4);
                size_t soff = (size_t)r*K + k0 + (ch<<3);
                cp16(bb + 32768 + doff, gB + soff);
            }
            cp_commit();
            cp_wait<1>();
        } else {
            cp_wait<0>();
        }
        __syncthreads();

        uint32_t tb = sb + (c&1)*MG_STAGE;
        uint32_t tAh = tb, tAl = tb + 16384, tB = tb + 32768;

        #pragma unroll
        for (int ks = 0; ks < 4; ks++){
            int ch0 = ks*2 + lch;
            uint32_t a_h[2][4], a_l[2][4], b_f[2][4];
            #pragma unroll
            for (int mt=0; mt<2; mt++){
                int row = wm*32 + mt*16 + lrow;
                uint32_t off = (row<<7) + ((ch0 ^ (row&7))<<4);
                ldsm4(tAh + off, a_h[mt]);
                ldsm4(tAl + off, a_l[mt]);
            }
            #pragma unroll
            for (int np=0; np<2; np++){
                int row = wn*32 + np*16 + lrow;
                uint32_t off = (row<<7) + ((ch0 ^ (row&7))<<4);
                ldsm4(tB + off, b_f[np]);
            }
            #pragma unroll
            for (int mt=0; mt<2; mt++){
                #pragma unroll
                for (int nt=0; nt<4; nt++){
                    int np = nt>>1, hf = nt&1;
                    uint32_t b0 = b_f[np][hf], b1 = b_f[np][hf+2];
                    mma16816h(acc[mt][nt], a_h[mt], b0, b1);
                    mma16816h(acc[mt][nt], a_l[mt], b0, b1);
                }
            }
        }
        __syncthreads();
    }

    int lr = lane >> 2, lc = (lane & 3) * 2;
    #pragma unroll
    for (int mt=0; mt<2; mt++){
        #pragma unroll
        for (int nt=0; nt<4; nt++){
            int col = col0 + wn*32 + nt*8 + lc;
            #pragma unroll
            for (int half=0; half<2; half++){
                int row = row0 + wm*32 + mt*16 + lr + half*8;
                float v0 = acc[mt][nt][half*2+0];
                float v1 = acc[mt][nt][half*2+1];
                if (MODE == 0){
                    float2 r; r.x = v0; r.y = v1;
                    *(float2*)(C + (size_t)row*M + col) = r;
                } else if (MODE == 2){
                    float2* cp = (float2*)(C + (size_t)row*M + col);
                    float2 o = *cp;
                    float2 r;
                    r.x = v0 + bias[col+0] + o.x;
                    r.y = v1 + bias[col+1] + o.y;
                    *cp = r;
                } else if (MODE == 4){
                    *(__half2*)(Oh + (size_t)row*M + col) = __floats2half2_rn(v0, v1);
                } else {
                    float a = gelu_tanh(v0 + bias[col+0]);
                    float b = gelu_tanh(v1 + bias[col+1]);
                    __half ha, la, hb, lb;
                    split2h(a, ha, la);
                    split2h(b, hb, lb);
                    *(__half2*)(Oh + (size_t)row*M + col) = __halves2half2(ha, hb);
                    *(__half2*)(Ol + (size_t)row*M + col) = __halves2half2(la, lb);
                }
            }
        }
    }
}

// ---------------- HMMA flash window attention ----------------
__global__ void __launch_bounds__(256, 1)
attn_kernel(const __half* __restrict__ qkvh,
            const float* __restrict__ btab_g,
            __half* __restrict__ outh,
            __half* __restrict__ outl, int shifted)
{
    __shared__ __half Qs[256*40];
    __shared__ __half Ks[64*40];
    __shared__ __half Vs[64*40];
    __shared__ float  btab[NBIAS];
    __shared__ int    sreg[256];

    int head = blockIdx.y;
    int bw = blockIdx.x;
    int b = bw / NWIN, w = bw % NWIN;
    int wd = w/49, wh = (w/7)%7, ww = w%7;
    int tid = threadIdx.x, lane = tid & 31, warp = tid >> 5;
    int lr = lane >> 2, lc = lane & 3;

    {
        int i = tid;
        int di = i>>6, hi = (i>>3)&7, wi = i&7;
        int dr = wd*4+di, hr = wh*8+hi, wr = ww*8+wi;
        int rd = dr<4?0:(dr<6?1:2);
        int rh = hr<48?0:(hr<52?1:2);
        int rw = wr<48?0:(wr<52?1:2);
        sreg[i] = rd*9 + rh*3 + rw;
        int d=dr, h=hr, w2=wr;
        if (shifted){ d=(dr+2)&7; h=(hr+4)%HPX; w2=(wr+4)%WPX; }
        int tok = ((b*DDIM + d)*HPX + h)*WPX + w2;
        const uint4* src = (const uint4*)(qkvh + (size_t)tok*768 + head*32);
        uint4* dst = (uint4*)(Qs + i*40);
        dst[0]=src[0]; dst[1]=src[1]; dst[2]=src[2]; dst[3]=src[3];
    }
    for (int t=tid; t<NBIAS; t+=256) btab[t] = btab_g[t*8 + head];
    __syncthreads();

    uint32_t qbase = smem_u32(Qs), kbase = smem_u32(Ks), vbase = smem_u32(Vs);

    uint32_t qa[2][2][4];
    #pragma unroll
    for (int mt=0; mt<2; mt++)
        #pragma unroll
        for (int kt=0; kt<2; kt++){
            int r = warp*32 + mt*16 + (lane&15);
            ldsm4(qbase + r*80 + (kt*16 + (lane>>4)*8)*2, qa[mt][kt]);
        }

    int rbase0[4], rmyreg[4], rtok[4];
    #pragma unroll
    for (int q=0; q<4; q++){
        int mt = q>>1, hf = q&1;
        int i = warp*32 + mt*16 + lr + hf*8;
        int di = i>>6, hi = (i>>3)&7, wi = i&7;
        int dr = wd*4+di, hr = wh*8+hi, wr = ww*8+wi;
        int rd = dr<4?0:(dr<6?1:2);
        int rh = hr<48?0:(hr<52?1:2);
        int rw = wr<48?0:(wr<52?1:2);
        rmyreg[q] = rd*9 + rh*3 + rw;
        rbase0[q] = (di+3)*225 + (hi+7)*15 + (wi+7);
        int d=dr, h=hr, w2=wr;
        if (shifted){ d=(dr+2)&7; h=(hr+4)%HPX; w2=(wr+4)%WPX; }
        rtok[q] = ((b*DDIM + d)*HPX + h)*WPX + w2;
    }

    float mrow[4], lrow[4];
    #pragma unroll
    for (int q=0; q<4; q++){ mrow[q] = -1e30f; lrow[q] = 0.f; }
    float o[2][4][4];
    #pragma unroll
    for (int mt=0; mt<2; mt++)
        #pragma unroll
        for (int nt=0; nt<4; nt++)
            #pragma unroll
            for (int k=0;k<4;k++) o[mt][nt][k] = 0.f;

    const float scale = 0.17677669529663687f;

    #pragma unroll 1
    for (int c = 0; c < 4; c++){
        __syncthreads();
        {
            int r = tid>>2, part = tid&3;
            int j = c*64 + r;
            int hi = (j>>3)&7, wi = j&7;
            int dr = wd*4+c, hr = wh*8+hi, wr = ww*8+wi;
            int d=dr, h=hr, w2=wr;
            if (shifted){ d=(dr+2)&7; h=(hr+4)%HPX; w2=(wr+4)%WPX; }
            int tok = ((b*DDIM + d)*HPX + h)*WPX + w2;
            const uint4* kv = (const uint4*)(qkvh + (size_t)tok*768 + 256 + head*32);
            const uint4* vv = (const uint4*)(qkvh + (size_t)tok*768 + 512 + head*32);
            *(uint4*)(Ks + r*40 + part*8) = kv[part];
            *(uint4*)(Vs + r*40 + part*8) = vv[part];
        }
        __syncthreads();

        float S[2][8][4];
        #pragma unroll
        for (int mt=0;mt<2;mt++)
            #pragma unroll
            for (int jt=0;jt<8;jt++)
                #pragma unroll
                for (int k=0;k<4;k++) S[mt][jt][k]=0.f;

        #pragma unroll
        for (int p=0; p<4; p++){
            uint32_t kf[2][4];
            #pragma unroll
            for (int kt=0; kt<2; kt++){
                int r = p*16 + (lane&15);
                ldsm4(kbase + r*80 + (kt*16 + (lane>>4)*8)*2, kf[kt]);
            }
            #pragma unroll
            for (int mt=0; mt<2; mt++)
                #pragma unroll
                for (int s=0; s<2; s++)
                    #pragma unroll
                    for (int kt=0; kt<2; kt++)
                        mma16816h(S[mt][p*2+s], qa[mt][kt], kf[kt][s], kf[kt][s+2]);
        }

        float mc[4];
        #pragma unroll
        for (int q=0;q<4;q++) mc[q] = -1e30f;
        #pragma unroll
        for (int mt=0; mt<2; mt++)
            #pragma unroll
            for (int jt=0; jt<8; jt++)
                #pragma unroll
                for (int idx=0; idx<4; idx++){
                    int q = mt*2 + (idx>>1);
                    int e = idx&1;
                    int rel = rbase0[q] - c*225 - jt*15 - (2*lc + e);
                    float s = fmaf(S[mt][jt][idx], scale, btab[rel]);
                    if (shifted && sreg[c*64 + jt*8 + 2*lc + e] != rmyreg[q]) s = -1e9f;
                    S[mt][jt][idx] = s;
                    mc[q] = fmaxf(mc[q], s);
                }
        #pragma unroll
        for (int q=0;q<4;q++){
            mc[q] = fmaxf(mc[q], __shfl_xor_sync(0xffffffffu, mc[q], 1));
            mc[q] = fmaxf(mc[q], __shfl_xor_sync(0xffffffffu, mc[q], 2));
        }

        float corr[4], sumc[4];
        #pragma unroll
        for (int q=0;q<4;q++){
            float mn = fmaxf(mrow[q], mc[q]);
            corr[q] = __expf(mrow[q] - mn);
            mrow[q] = mn;
            sumc[q] = 0.f;
        }
        uint32_t pa[2][4][4];
        #pragma unroll
        for (int mt=0; mt<2; mt++)
            #pragma unroll
            for (int kt2=0; kt2<4; kt2++){
                int jtA = kt2*2, jtB = kt2*2+1;
                float pA0 = __expf(S[mt][jtA][0]-mrow[mt*2]);
                float pA1 = __expf(S[mt][jtA][1]-mrow[mt*2]);
                float pA2 = __expf(S[mt][jtA][2]-mrow[mt*2+1]);
                float pA3 = __expf(S[mt][jtA][3]-mrow[mt*2+1]);
                float pB0 = __expf(S[mt][jtB][0]-mrow[mt*2]);
                float pB1 = __expf(S[mt][jtB][1]-mrow[mt*2]);
                float pB2 = __expf(S[mt][jtB][2]-mrow[mt*2+1]);
                float pB3 = __expf(S[mt][jtB][3]-mrow[mt*2+1]);
                sumc[mt*2+0] += pA0 + pA1 + pB0 + pB1;
                sumc[mt*2+1] += pA2 + pA3 + pB2 + pB3;
                __half2 a0 = __floats2half2_rn(pA0, pA1);
                __half2 a1 = __floats2half2_rn(pA2, pA3);
                __half2 a2 = __floats2half2_rn(pB0, pB1);
                __half2 a3 = __floats2half2_rn(pB2, pB3);
                pa[mt][kt2][0] = *(uint32_t*)&a0;
                pa[mt][kt2][1] = *(uint32_t*)&a1;
                pa[mt][kt2][2] = *(uint32_t*)&a2;
                pa[mt][kt2][3] = *(uint32_t*)&a3;
            }
        #pragma unroll
        for (int q=0;q<4;q++){
            sumc[q] += __shfl_xor_sync(0xffffffffu, sumc[q], 1);
            sumc[q] += __shfl_xor_sync(0xffffffffu, sumc[q], 2);
            lrow[q] = lrow[q]*corr[q] + sumc[q];
        }
        #pragma unroll
        for (int mt=0; mt<2; mt++)
            #pragma unroll
            for (int nt=0; nt<4; nt++){
                o[mt][nt][0] *= corr[mt*2+0];
                o[mt][nt][1] *= corr[mt*2+0];
                o[mt][nt][2] *= corr[mt*2+1];
                o[mt][nt][3] *= corr[mt*2+1];
            }

        #pragma unroll
        for (int dp=0; dp<2; dp++){
            uint32_t vl[4][4];
            #pragma unroll
            for (int kt2=0; kt2<4; kt2++){
                uint32_t addr = vbase + (kt2*16 + ((lane>>3)&1)*8 + (lane&7))*80
                              + (dp*16 + (lane>>4)*8)*2;
                ldsm4t(addr, vl[kt2]);
            }
            #pragma unroll
            for (int s=0; s<2; s++){
                int nt = dp*2 + s;
                #pragma unroll
                for (int mt=0; mt<2; mt++)
                    #pragma unroll
                    for (int kt2=0; kt2<4; kt2++)
                        mma16816h(o[mt][nt], pa[mt][kt2], vl[kt2][2*s], vl[kt2][2*s+1]);
            }
        }
    }

    float inv[4];
    #pragma unroll
    for (int q=0;q<4;q++) inv[q] = 1.f/lrow[q];
    #pragma unroll
    for (int mt=0; mt<2; mt++)
        #pragma unroll
        for (int nt=0; nt<4; nt++){
            int col = head*32 + nt*8 + 2*lc;
            #pragma unroll
            for (int hf=0; hf<2; hf++){
                int q = mt*2 + hf;
                float v0 = o[mt][nt][hf*2+0]*inv[q];
                float v1 = o[mt][nt][hf*2+1]*inv[q];
                __half h0,l0,h1,l1;
                split2h(v0, h0, l0);
                split2h(v1, h1, l1);
                size_t off = (size_t)rtok[q]*CDIM + col;
                *(__half2*)(outh + off) = __halves2half2(h0, h1);
                *(__half2*)(outl + off) = __halves2half2(l0, l1);
            }
        }
}

// ---------------- final transpose: tiled, coalesced ----------------
__global__ void to_out_kernel(const float* __restrict__ y, float* __restrict__ out)
{
    __shared__ float tile[32][33];
    int b = blockIdx.z;
    int c0 = blockIdx.y*32, s0 = blockIdx.x*32;
    int tx = threadIdx.x & 31, ty = threadIdx.x >> 5;
    #pragma unroll
    for (int i=0;i<4;i++)
        tile[ty + i*8][tx] = y[((size_t)b*NSPAT + s0 + ty + i*8)*CDIM + c0 + tx];
    __syncthreads();
    #pragma unroll
    for (int i=0;i<4;i++)
        out[((size_t)(b*CDIM + c0 + ty + i*8))*NSPAT + s0 + tx] = tile[tx][ty + i*8];
}

// ---------------- launch ----------------
extern "C" void kernel_launch(void* const* d_in, const int* in_sizes, int n_in,
                              void* d_out, int out_size)
{
    const float* x      = (const float*)d_in[0];
    const float* conv_w = (const float*)d_in[1];
    const float* conv_b = (const float*)d_in[2];
    const float* ln1_s  = (const float*)d_in[3];
    const float* ln1_b  = (const float*)d_in[4];
    const float* qkv_w  = (const float*)d_in[5];
    const float* out_w  = (const float*)d_in[6];
    const float* out_b  = (const float*)d_in[7];
    const float* bias_t = (const float*)d_in[8];
    const float* ln2_s  = (const float*)d_in[9];
    const float* ln2_b  = (const float*)d_in[10];
    const float* fc1_w  = (const float*)d_in[11];
    const float* fc1_b  = (const float*)d_in[12];
    const float* fc2_w  = (const float*)d_in[13];
    const float* fc2_b  = (const float*)d_in[14];
    float* out = (float*)d_out;

    cudaFuncSetAttribute(mgemm_kernel<0>, cudaFuncAttributeMaxDynamicSharedMemorySize, MG_TOTAL);
    cudaFuncSetAttribute(mgemm_kernel<2>, cudaFuncAttributeMaxDynamicSharedMemorySize, MG_TOTAL);
    cudaFuncSetAttribute(mgemm_kernel<3>, cudaFuncAttributeMaxDynamicSharedMemorySize, MG_TOTAL);
    cudaFuncSetAttribute(mgemm_kernel<4>, cudaFuncAttributeMaxDynamicSharedMemorySize, MG_TOTAL);

    float *gy;
    __half *gqkvh, *gah, *gal, *gbh, *gbl;
    __half *wq, *wo, *w1, *w2;
    cudaGetSymbolAddress((void**)&gy,    g_y);
    cudaGetSymbolAddress((void**)&gqkvh, g_qkvh);
    cudaGetSymbolAddress((void**)&gah,   g_ah);
    cudaGetSymbolAddress((void**)&gal,   g_al);
    cudaGetSymbolAddress((void**)&gbh,   g_bh);
    cudaGetSymbolAddress((void**)&gbl,   g_bl);
    cudaGetSymbolAddress((void**)&wq,    w_qkv);
    cudaGetSymbolAddress((void**)&wo,    w_out);
    cudaGetSymbolAddress((void**)&w1,    w_fc1);
    cudaGetSymbolAddress((void**)&w2,    w_fc2);

    wprep_kernel<<<dim3(512,4), 256>>>(qkv_w, wq, 256, 768);
    wprep_kernel<<<dim3(512,4), 256>>>(out_w, wo, 256, 256);
    wprep_kernel<<<dim3(512,4), 256>>>(fc1_w, w1, 256, 1024);
    wprep_kernel<<<dim3(512,4), 256>>>(fc2_w, w2, 1024, 256);

    patch_embed_kernel<<<NTOK, 256>>>(x, conv_w, conv_b, gy);

    for (int L=0; L<4; L++){
        int shifted = L & 1;
        ln_kernel<<<NTOK/8, 256>>>(gy, gah, gal, ln1_s + L*256, ln1_b + L*256);
        mgemm_kernel<4><<<dim3(12, 392), 256, MG_TOTAL>>>(gah, gal,
            wq + (size_t)L*768*256,
            nullptr, nullptr, gqkvh, nullptr, 768, 256);
        attn_kernel<<<dim3(BATCH*NWIN, 8), 256>>>(gqkvh, bias_t + (size_t)L*NBIAS*8, gah, gal, shifted);
        mgemm_kernel<2><<<dim3(4, 392), 256, MG_TOTAL>>>(gah, gal,
            wo + (size_t)L*256*256,
            out_b + L*256, gy, nullptr, nullptr, 256, 256);
        ln_kernel<<<NTOK/8, 256>>>(gy, gah, gal, ln2_s + L*256, ln2_b + L*256);
        mgemm_kernel<3><<<dim3(16, 392), 256, MG_TOTAL>>>(gah, gal,
            w1 + (size_t)L*1024*256,
            fc1_b + L*1024, nullptr, gbh, gbl, 1024, 256);
        mgemm_kernel<2><<<dim3(4, 392), 256, MG_TOTAL>>>(gbh, gbl,
            w2 + (size_t)L*256*1024,
            fc2_b + L*256, gy, nullptr, nullptr, 256, 1024);
    }

    to_out_kernel<<<dim3(NSPAT/32, CDIM/32, BATCH), 256>>>(gy, out);
}

// round 12
// speedup vs baseline: 2.7422x; 1.1708x over previous
#include <cuda_runtime.h>
#include <cuda_fp16.h>
#include <cstdint>

// ---------------- problem constants ----------------
#define BATCH 2
#define DDIM  8
#define HPX   56
#define WPX   56
#define CDIM  256
#define NTOK  (BATCH*DDIM*HPX*WPX)   // 50176
#define NSPAT (DDIM*HPX*WPX)         // 25088
#define NWIN  98
#define NBIAS 1575
#define MLPD  1024

// ---------------- scratch ----------------
__device__ float g_y  [NTOK*CDIM];        // residual stream, fp32
__device__ __half g_qkvh[NTOK*3*CDIM];    // qkv projections fp16
__device__ __half g_a[NTOK*CDIM];         // activations fp16 (LN out / attn out)
__device__ __half g_b[NTOK*MLPD];         // gelu out (fc2 input)
// transposed fp16 weights: [M_out, K] K-major
__device__ __half w_qkv[4*768*256];
__device__ __half w_out[4*256*256];
__device__ __half w_fc1[4*1024*256];
__device__ __half w_fc2[4*256*1024];

// ---------------- helpers ----------------
__device__ __forceinline__ uint32_t smem_u32(const void* p){
    uint32_t a;
    asm("{ .reg .u64 t; cvta.to.shared.u64 t, %1; cvt.u32.u64 %0, t; }" : "=r"(a) : "l"(p));
    return a;
}
__device__ __forceinline__ void cp16(uint32_t dst, const void* src){
    asm volatile("cp.async.cg.shared.global [%0], [%1], 16;" :: "r"(dst), "l"(src));
}
__device__ __forceinline__ void cp_commit(){
    asm volatile("cp.async.commit_group;" ::: "memory");
}
template<int N>
__device__ __forceinline__ void cp_wait(){
    asm volatile("cp.async.wait_group %0;" :: "n"(N) : "memory");
}
__device__ __forceinline__ void ldsm4(uint32_t addr, uint32_t* r){
    asm volatile("ldmatrix.sync.aligned.m8n8.x4.shared.b16 {%0,%1,%2,%3}, [%4];"
        : "=r"(r[0]), "=r"(r[1]), "=r"(r[2]), "=r"(r[3]) : "r"(addr));
}
__device__ __forceinline__ void ldsm4t(uint32_t addr, uint32_t* r){
    asm volatile("ldmatrix.sync.aligned.m8n8.x4.trans.shared.b16 {%0,%1,%2,%3}, [%4];"
        : "=r"(r[0]), "=r"(r[1]), "=r"(r[2]), "=r"(r[3]) : "r"(addr));
}
__device__ __forceinline__ void mma16816h(float* c, const uint32_t* a, uint32_t b0, uint32_t b1){
    asm volatile("mma.sync.aligned.m16n8k16.row.col.f32.f16.f16.f32 "
        "{%0,%1,%2,%3}, {%4,%5,%6,%7}, {%8,%9}, {%0,%1,%2,%3};"
        : "+f"(c[0]), "+f"(c[1]), "+f"(c[2]), "+f"(c[3])
        : "r"(a[0]), "r"(a[1]), "r"(a[2]), "r"(a[3]), "r"(b0), "r"(b1));
}
__device__ __forceinline__ float gelu_tanh(float x){
    float x3 = x*x*x;
    return 0.5f*x*(1.f + tanhf(0.7978845608028654f*(x + 0.044715f*x3)));
}

// ---------------- weight prep: W[K,M] fp32 -> Wt[M,K] fp16 ----------------
__global__ void wprep_kernel(const float* __restrict__ W, __half* __restrict__ oh,
                             int K, int M)
{
    int ly = blockIdx.y;
    size_t n = (size_t)K*M;
    const float* w = W + ly*n;
    __half* h = oh + ly*n;
    for (size_t i = (size_t)blockIdx.x*blockDim.x + threadIdx.x; i < n; i += (size_t)gridDim.x*blockDim.x){
        int k = (int)(i / M), m = (int)(i % M);
        h[(size_t)m*K + k] = __float2half_rn(w[i]);
    }
}

// ---------------- patch embed ----------------
__global__ void patch_embed_kernel(const float* __restrict__ x,
                                   const float* __restrict__ w,
                                   const float* __restrict__ b,
                                   float* __restrict__ y)
{
    int t = blockIdx.x;
    int wp = t % WPX, hp = (t/WPX) % HPX, d = (t/(WPX*HPX)) % DDIM, bb = t/(WPX*HPX*DDIM);
    __shared__ float patch[64];
    int tid = threadIdx.x;
    if (tid < 64){
        int ic = tid>>4, kh = (tid>>2)&3, kw = tid&3;
        patch[tid] = x[ (((size_t)(bb*4+ic)*DDIM + d)*224 + hp*4+kh)*224 + wp*4+kw ];
    }
    __syncthreads();
    float acc = b[tid];
    const float* wr = w + tid*64;
    #pragma unroll
    for (int k=0;k<64;k++) acc += patch[k]*wr[k];
    y[(size_t)t*CDIM + tid] = acc;
}

// ---------------- layernorm: warp per token, 8 tokens/block, fp16 out ----------------
__global__ void ln_kernel(const float* __restrict__ in,
                          __half* __restrict__ oh,
                          const float* __restrict__ sc, const float* __restrict__ bi)
{
    int warp = threadIdx.x >> 5, lane = threadIdx.x & 31;
    int t = blockIdx.x*8 + warp;
    const float4* row = (const float4*)(in + (size_t)t*CDIM);
    float4 a = row[lane*2], b = row[lane*2+1];
    float s1 = a.x+a.y+a.z+a.w + b.x+b.y+b.z+b.w;
    float s2 = a.x*a.x+a.y*a.y+a.z*a.z+a.w*a.w + b.x*b.x+b.y*b.y+b.z*b.z+b.w*b.w;
    #pragma unroll
    for (int o=16;o;o>>=1){
        s1 += __shfl_xor_sync(0xffffffffu, s1, o);
        s2 += __shfl_xor_sync(0xffffffffu, s2, o);
    }
    float mean = s1*(1.f/256.f);
    float var  = s2*(1.f/256.f) - mean*mean;
    float rs = rsqrtf(var + 1e-5f);
    int c0 = lane*8;
    float4 sca = *(const float4*)(sc + c0), scb = *(const float4*)(sc + c0 + 4);
    float4 bia = *(const float4*)(bi + c0), bib = *(const float4*)(bi + c0 + 4);
    __half2 hh[4];
    hh[0] = __floats2half2_rn((a.x-mean)*rs*sca.x+bia.x, (a.y-mean)*rs*sca.y+bia.y);
    hh[1] = __floats2half2_rn((a.z-mean)*rs*sca.z+bia.z, (a.w-mean)*rs*sca.w+bia.w);
    hh[2] = __floats2half2_rn((b.x-mean)*rs*scb.x+bib.x, (b.y-mean)*rs*scb.y+bib.y);
    hh[3] = __floats2half2_rn((b.z-mean)*rs*scb.z+bib.z, (b.w-mean)*rs*scb.w+bib.w);
    *(uint4*)(oh + (size_t)t*CDIM + c0) = *(uint4*)hh;
}

// ---------------- HMMA fp16 1-term GEMM ----------------
// A (act): [NTOK, K] fp16 K-major.  B (weight): [M, K] fp16 K-major.
// CTA: 128 rows x 64 cols, 256 threads = 8 warps (4m x 2n), warp tile 32x32.
// K chunks of 64, double-buffered cp.async; stage = A16K|B8K = 24KB, 2 stages = 48KB.
// MODE 0: fp32 out. MODE 2: bias+residual fp32. MODE 3: bias+gelu -> fp16.
// MODE 4: fp16 out (no bias) — qkv path.
#define MG_STAGE 24576
#define MG_TOTAL 49152

template<int MODE>
__global__ void __launch_bounds__(256, 2)
mgemm_kernel(const __half* __restrict__ A,
             const __half* __restrict__ B,
             const float* __restrict__ bias, float* __restrict__ C,
             __half* __restrict__ Oh,
             int M, int K)
{
    extern __shared__ char smem[];
    uint32_t sb = smem_u32(smem);
    int tid = threadIdx.x, lane = tid & 31, wid = tid >> 5;
    int wm = wid & 3, wn = wid >> 2;
    int row0 = blockIdx.y*128, col0 = blockIdx.x*64;

    const __half* gA = A + (size_t)row0*K;
    const __half* gB = B + (size_t)col0*K;

    float acc[2][4][4];
    #pragma unroll
    for (int i=0;i<2;i++)
        #pragma unroll
        for (int j=0;j<4;j++)
            #pragma unroll
            for (int k=0;k<4;k++) acc[i][j][k]=0.f;

    int lrow = lane & 15, lch = lane >> 4;
    int nchunk = K >> 6;

    // prologue: chunk 0 -> stage 0
    {
        uint32_t bb = sb;
        #pragma unroll
        for (int h=0; h<4; h++){
            int i = tid + (h<<8);
            int r = i>>3, ch = i&7;
            uint32_t doff = (r<<7) + ((ch ^ (r&7))<<4);
            cp16(bb + doff, gA + (size_t)r*K + (ch<<3));
        }
        #pragma unroll
        for (int h=0; h<2; h++){
            int i = tid + (h<<8);
            int r = i>>3, ch = i&7;
            uint32_t doff = (r<<7) + ((ch ^ (r&7))<<4);
            cp16(bb + 16384 + doff, gB + (size_t)r*K + (ch<<3));
        }
        cp_commit();
    }

    #pragma unroll 1
    for (int c = 0; c < nchunk; c++){
        if (c+1 < nchunk){
            int k0 = (c+1) << 6;
            uint32_t bb = sb + ((c+1)&1)*MG_STAGE;
            #pragma unroll
            for (int h=0; h<4; h++){
                int i = tid + (h<<8);
                int r = i>>3, ch = i&7;
                uint32_t doff = (r<<7) + ((ch ^ (r&7))<<4);
                cp16(bb + doff, gA + (size_t)r*K + k0 + (ch<<3));
            }
            #pragma unroll
            for (int h=0; h<2; h++){
                int i = tid + (h<<8);
                int r = i>>3, ch = i&7;
                uint32_t doff = (r<<7) + ((ch ^ (r&7))<<4);
                cp16(bb + 16384 + doff, gB + (size_t)r*K + k0 + (ch<<3));
            }
            cp_commit();
            cp_wait<1>();
        } else {
            cp_wait<0>();
        }
        __syncthreads();

        uint32_t tb = sb + (c&1)*MG_STAGE;
        uint32_t tA = tb, tB = tb + 16384;

        #pragma unroll
        for (int ks = 0; ks < 4; ks++){
            int ch0 = ks*2 + lch;
            uint32_t a_f[2][4], b_f[2][4];
            #pragma unroll
            for (int mt=0; mt<2; mt++){
                int row = wm*32 + mt*16 + lrow;
                uint32_t off = (row<<7) + ((ch0 ^ (row&7))<<4);
                ldsm4(tA + off, a_f[mt]);
            }
            #pragma unroll
            for (int np=0; np<2; np++){
                int row = wn*32 + np*16 + lrow;
                uint32_t off = (row<<7) + ((ch0 ^ (row&7))<<4);
                ldsm4(tB + off, b_f[np]);
            }
            #pragma unroll
            for (int mt=0; mt<2; mt++){
                #pragma unroll
                for (int nt=0; nt<4; nt++){
                    int np = nt>>1, hf = nt&1;
                    mma16816h(acc[mt][nt], a_f[mt], b_f[np][hf], b_f[np][hf+2]);
                }
            }
        }
        __syncthreads();
    }

    int lr = lane >> 2, lc = (lane & 3) * 2;
    #pragma unroll
    for (int mt=0; mt<2; mt++){
        #pragma unroll
        for (int nt=0; nt<4; nt++){
            int col = col0 + wn*32 + nt*8 + lc;
            #pragma unroll
            for (int half=0; half<2; half++){
                int row = row0 + wm*32 + mt*16 + lr + half*8;
                float v0 = acc[mt][nt][half*2+0];
                float v1 = acc[mt][nt][half*2+1];
                if (MODE == 0){
                    float2 r; r.x = v0; r.y = v1;
                    *(float2*)(C + (size_t)row*M + col) = r;
                } else if (MODE == 2){
                    float2* cp = (float2*)(C + (size_t)row*M + col);
                    float2 o = *cp;
                    float2 r;
                    r.x = v0 + bias[col+0] + o.x;
                    r.y = v1 + bias[col+1] + o.y;
                    *cp = r;
                } else if (MODE == 4){
                    *(__half2*)(Oh + (size_t)row*M + col) = __floats2half2_rn(v0, v1);
                } else {
                    float a = gelu_tanh(v0 + bias[col+0]);
                    float b = gelu_tanh(v1 + bias[col+1]);
                    *(__half2*)(Oh + (size_t)row*M + col) = __floats2half2_rn(a, b);
                }
            }
        }
    }
}

// ---------------- HMMA flash window attention (fp16 out) ----------------
__global__ void __launch_bounds__(256, 1)
attn_kernel(const __half* __restrict__ qkvh,
            const float* __restrict__ btab_g,
            __half* __restrict__ outh, int shifted)
{
    __shared__ __half Qs[256*40];
    __shared__ __half Ks[64*40];
    __shared__ __half Vs[64*40];
    __shared__ float  btab[NBIAS];
    __shared__ int    sreg[256];

    int head = blockIdx.y;
    int bw = blockIdx.x;
    int b = bw / NWIN, w = bw % NWIN;
    int wd = w/49, wh = (w/7)%7, ww = w%7;
    int tid = threadIdx.x, lane = tid & 31, warp = tid >> 5;
    int lr = lane >> 2, lc = lane & 3;

    {
        int i = tid;
        int di = i>>6, hi = (i>>3)&7, wi = i&7;
        int dr = wd*4+di, hr = wh*8+hi, wr = ww*8+wi;
        int rd = dr<4?0:(dr<6?1:2);
        int rh = hr<48?0:(hr<52?1:2);
        int rw = wr<48?0:(wr<52?1:2);
        sreg[i] = rd*9 + rh*3 + rw;
        int d=dr, h=hr, w2=wr;
        if (shifted){ d=(dr+2)&7; h=(hr+4)%HPX; w2=(wr+4)%WPX; }
        int tok = ((b*DDIM + d)*HPX + h)*WPX + w2;
        const uint4* src = (const uint4*)(qkvh + (size_t)tok*768 + head*32);
        uint4* dst = (uint4*)(Qs + i*40);
        dst[0]=src[0]; dst[1]=src[1]; dst[2]=src[2]; dst[3]=src[3];
    }
    for (int t=tid; t<NBIAS; t+=256) btab[t] = btab_g[t*8 + head];
    __syncthreads();

    uint32_t qbase = smem_u32(Qs), kbase = smem_u32(Ks), vbase = smem_u32(Vs);

    uint32_t qa[2][2][4];
    #pragma unroll
    for (int mt=0; mt<2; mt++)
        #pragma unroll
        for (int kt=0; kt<2; kt++){
            int r = warp*32 + mt*16 + (lane&15);
            ldsm4(qbase + r*80 + (kt*16 + (lane>>4)*8)*2, qa[mt][kt]);
        }

    int rbase0[4], rmyreg[4], rtok[4];
    #pragma unroll
    for (int q=0; q<4; q++){
        int mt = q>>1, hf = q&1;
        int i = warp*32 + mt*16 + lr + hf*8;
        int di = i>>6, hi = (i>>3)&7, wi = i&7;
        int dr = wd*4+di, hr = wh*8+hi, wr = ww*8+wi;
        int rd = dr<4?0:(dr<6?1:2);
        int rh = hr<48?0:(hr<52?1:2);
        int rw = wr<48?0:(wr<52?1:2);
        rmyreg[q] = rd*9 + rh*3 + rw;
        rbase0[q] = (di+3)*225 + (hi+7)*15 + (wi+7);
        int d=dr, h=hr, w2=wr;
        if (shifted){ d=(dr+2)&7; h=(hr+4)%HPX; w2=(wr+4)%WPX; }
        rtok[q] = ((b*DDIM + d)*HPX + h)*WPX + w2;
    }

    float mrow[4], lrow[4];
    #pragma unroll
    for (int q=0; q<4; q++){ mrow[q] = -1e30f; lrow[q] = 0.f; }
    float o[2][4][4];
    #pragma unroll
    for (int mt=0; mt<2; mt++)
        #pragma unroll
        for (int nt=0; nt<4; nt++)
            #pragma unroll
            for (int k=0;k<4;k++) o[mt][nt][k] = 0.f;

    const float scale = 0.17677669529663687f;

    #pragma unroll 1
    for (int c = 0; c < 4; c++){
        __syncthreads();
        {
            int r = tid>>2, part = tid&3;
            int j = c*64 + r;
            int hi = (j>>3)&7, wi = j&7;
            int dr = wd*4+c, hr = wh*8+hi, wr = ww*8+wi;
            int d=dr, h=hr, w2=wr;
            if (shifted){ d=(dr+2)&7; h=(hr+4)%HPX; w2=(wr+4)%WPX; }
            int tok = ((b*DDIM + d)*HPX + h)*WPX + w2;
            const uint4* kv = (const uint4*)(qkvh + (size_t)tok*768 + 256 + head*32);
            const uint4* vv = (const uint4*)(qkvh + (size_t)tok*768 + 512 + head*32);
            *(uint4*)(Ks + r*40 + part*8) = kv[part];
            *(uint4*)(Vs + r*40 + part*8) = vv[part];
        }
        __syncthreads();

        float S[2][8][4];
        #pragma unroll
        for (int mt=0;mt<2;mt++)
            #pragma unroll
            for (int jt=0;jt<8;jt++)
                #pragma unroll
                for (int k=0;k<4;k++) S[mt][jt][k]=0.f;

        #pragma unroll
        for (int p=0; p<4; p++){
            uint32_t kf[2][4];
            #pragma unroll
            for (int kt=0; kt<2; kt++){
                int r = p*16 + (lane&15);
                ldsm4(kbase + r*80 + (kt*16 + (lane>>4)*8)*2, kf[kt]);
            }
            #pragma unroll
            for (int mt=0; mt<2; mt++)
                #pragma unroll
                for (int s=0; s<2; s++)
                    #pragma unroll
                    for (int kt=0; kt<2; kt++)
                        mma16816h(S[mt][p*2+s], qa[mt][kt], kf[kt][s], kf[kt][s+2]);
        }

        float mc[4];
        #pragma unroll
        for (int q=0;q<4;q++) mc[q] = -1e30f;
        #pragma unroll
        for (int mt=0; mt<2; mt++)
            #pragma unroll
            for (int jt=0; jt<8; jt++)
                #pragma unroll
                for (int idx=0; idx<4; idx++){
                    int q = mt*2 + (idx>>1);
                    int e = idx&1;
                    int rel = rbase0[q] - c*225 - jt*15 - (2*lc + e);
                    float s = fmaf(S[mt][jt][idx], scale, btab[rel]);
                    if (shifted && sreg[c*64 + jt*8 + 2*lc + e] != rmyreg[q]) s = -1e9f;
                    S[mt][jt][idx] = s;
                    mc[q] = fmaxf(mc[q], s);
                }
        #pragma unroll
        for (int q=0;q<4;q++){
            mc[q] = fmaxf(mc[q], __shfl_xor_sync(0xffffffffu, mc[q], 1));
            mc[q] = fmaxf(mc[q], __shfl_xor_sync(0xffffffffu, mc[q], 2));
        }

        float corr[4], sumc[4];
        #pragma unroll
        for (int q=0;q<4;q++){
            float mn = fmaxf(mrow[q], mc[q]);
            corr[q] = __expf(mrow[q] - mn);
            mrow[q] = mn;
            sumc[q] = 0.f;
        }
        uint32_t pa[2][4][4];
        #pragma unroll
        for (int mt=0; mt<2; mt++)
            #pragma unroll
            for (int kt2=0; kt2<4; kt2++){
                int jtA = kt2*2, jtB = kt2*2+1;
                float pA0 = __expf(S[mt][jtA][0]-mrow[mt*2]);
                float pA1 = __expf(S[mt][jtA][1]-mrow[mt*2]);
                float pA2 = __expf(S[mt][jtA][2]-mrow[mt*2+1]);
                float pA3 = __expf(S[mt][jtA][3]-mrow[mt*2+1]);
                float pB0 = __expf(S[mt][jtB][0]-mrow[mt*2]);
                float pB1 = __expf(S[mt][jtB][1]-mrow[mt*2]);
                float pB2 = __expf(S[mt][jtB][2]-mrow[mt*2+1]);
                float pB3 = __expf(S[mt][jtB][3]-mrow[mt*2+1]);
                sumc[mt*2+0] += pA0 + pA1 + pB0 + pB1;
                sumc[mt*2+1] += pA2 + pA3 + pB2 + pB3;
                __half2 a0 = __floats2half2_rn(pA0, pA1);
                __half2 a1 = __floats2half2_rn(pA2, pA3);
                __half2 a2 = __floats2half2_rn(pB0, pB1);
                __half2 a3 = __floats2half2_rn(pB2, pB3);
                pa[mt][kt2][0] = *(uint32_t*)&a0;
                pa[mt][kt2][1] = *(uint32_t*)&a1;
                pa[mt][kt2][2] = *(uint32_t*)&a2;
                pa[mt][kt2][3] = *(uint32_t*)&a3;
            }
        #pragma unroll
        for (int q=0;q<4;q++){
            sumc[q] += __shfl_xor_sync(0xffffffffu, sumc[q], 1);
            sumc[q] += __shfl_xor_sync(0xffffffffu, sumc[q], 2);
            lrow[q] = lrow[q]*corr[q] + sumc[q];
        }
        #pragma unroll
        for (int mt=0; mt<2; mt++)
            #pragma unroll
            for (int nt=0; nt<4; nt++){
                o[mt][nt][0] *= corr[mt*2+0];
                o[mt][nt][1] *= corr[mt*2+0];
                o[mt][nt][2] *= corr[mt*2+1];
                o[mt][nt][3] *= corr[mt*2+1];
            }

        #pragma unroll
        for (int dp=0; dp<2; dp++){
            uint32_t vl[4][4];
            #pragma unroll
            for (int kt2=0; kt2<4; kt2++){
                uint32_t addr = vbase + (kt2*16 + ((lane>>3)&1)*8 + (lane&7))*80
                              + (dp*16 + (lane>>4)*8)*2;
                ldsm4t(addr, vl[kt2]);
            }
            #pragma unroll
            for (int s=0; s<2; s++){
                int nt = dp*2 + s;
                #pragma unroll
                for (int mt=0; mt<2; mt++)
                    #pragma unroll
                    for (int kt2=0; kt2<4; kt2++)
                        mma16816h(o[mt][nt], pa[mt][kt2], vl[kt2][2*s], vl[kt2][2*s+1]);
            }
        }
    }

    float inv[4];
    #pragma unroll
    for (int q=0;q<4;q++) inv[q] = 1.f/lrow[q];
    #pragma unroll
    for (int mt=0; mt<2; mt++)
        #pragma unroll
        for (int nt=0; nt<4; nt++){
            int col = head*32 + nt*8 + 2*lc;
            #pragma unroll
            for (int hf=0; hf<2; hf++){
                int q = mt*2 + hf;
                float v0 = o[mt][nt][hf*2+0]*inv[q];
                float v1 = o[mt][nt][hf*2+1]*inv[q];
                *(__half2*)(outh + (size_t)rtok[q]*CDIM + col) = __floats2half2_rn(v0, v1);
            }
        }
}

// ---------------- final transpose: tiled, coalesced ----------------
__global__ void to_out_kernel(const float* __restrict__ y, float* __restrict__ out)
{
    __shared__ float tile[32][33];
    int b = blockIdx.z;
    int c0 = blockIdx.y*32, s0 = blockIdx.x*32;
    int tx = threadIdx.x & 31, ty = threadIdx.x >> 5;
    #pragma unroll
    for (int i=0;i<4;i++)
        tile[ty + i*8][tx] = y[((size_t)b*NSPAT + s0 + ty + i*8)*CDIM + c0 + tx];
    __syncthreads();
    #pragma unroll
    for (int i=0;i<4;i++)
        out[((size_t)(b*CDIM + c0 + ty + i*8))*NSPAT + s0 + tx] = tile[tx][ty + i*8];
}

// ---------------- launch ----------------
extern "C" void kernel_launch(void* const* d_in, const int* in_sizes, int n_in,
                              void* d_out, int out_size)
{
    const float* x      = (const float*)d_in[0];
    const float* conv_w = (const float*)d_in[1];
    const float* conv_b = (const float*)d_in[2];
    const float* ln1_s  = (const float*)d_in[3];
    const float* ln1_b  = (const float*)d_in[4];
    const float* qkv_w  = (const float*)d_in[5];
    const float* out_w  = (const float*)d_in[6];
    const float* out_b  = (const float*)d_in[7];
    const float* bias_t = (const float*)d_in[8];
    const float* ln2_s  = (const float*)d_in[9];
    const float* ln2_b  = (const float*)d_in[10];
    const float* fc1_w  = (const float*)d_in[11];
    const float* fc1_b  = (const float*)d_in[12];
    const float* fc2_w  = (const float*)d_in[13];
    const float* fc2_b  = (const float*)d_in[14];
    float* out = (float*)d_out;

    cudaFuncSetAttribute(mgemm_kernel<0>, cudaFuncAttributeMaxDynamicSharedMemorySize, MG_TOTAL);
    cudaFuncSetAttribute(mgemm_kernel<2>, cudaFuncAttributeMaxDynamicSharedMemorySize, MG_TOTAL);
    cudaFuncSetAttribute(mgemm_kernel<3>, cudaFuncAttributeMaxDynamicSharedMemorySize, MG_TOTAL);
    cudaFuncSetAttribute(mgemm_kernel<4>, cudaFuncAttributeMaxDynamicSharedMemorySize, MG_TOTAL);

    float *gy;
    __half *gqkvh, *ga, *gb;
    __half *wq, *wo, *w1, *w2;
    cudaGetSymbolAddress((void**)&gy,    g_y);
    cudaGetSymbolAddress((void**)&gqkvh, g_qkvh);
    cudaGetSymbolAddress((void**)&ga,    g_a);
    cudaGetSymbolAddress((void**)&gb,    g_b);
    cudaGetSymbolAddress((void**)&wq,    w_qkv);
    cudaGetSymbolAddress((void**)&wo,    w_out);
    cudaGetSymbolAddress((void**)&w1,    w_fc1);
    cudaGetSymbolAddress((void**)&w2,    w_fc2);

    wprep_kernel<<<dim3(512,4), 256>>>(qkv_w, wq, 256, 768);
    wprep_kernel<<<dim3(512,4), 256>>>(out_w, wo, 256, 256);
    wprep_kernel<<<dim3(512,4), 256>>>(fc1_w, w1, 256, 1024);
    wprep_kernel<<<dim3(512,4), 256>>>(fc2_w, w2, 1024, 256);

    patch_embed_kernel<<<NTOK, 256>>>(x, conv_w, conv_b, gy);

    for (int L=0; L<4; L++){
        int shifted = L & 1;
        ln_kernel<<<NTOK/8, 256>>>(gy, ga, ln1_s + L*256, ln1_b + L*256);
        mgemm_kernel<4><<<dim3(12, 392), 256, MG_TOTAL>>>(ga,
            wq + (size_t)L*768*256,
            nullptr, nullptr, gqkvh, 768, 256);
        attn_kernel<<<dim3(BATCH*NWIN, 8), 256>>>(gqkvh, bias_t + (size_t)L*NBIAS*8, ga, shifted);
        mgemm_kernel<2><<<dim3(4, 392), 256, MG_TOTAL>>>(ga,
            wo + (size_t)L*256*256,
            out_b + L*256, gy, nullptr, 256, 256);
        ln_kernel<<<NTOK/8, 256>>>(gy, ga, ln2_s + L*256, ln2_b + L*256);
        mgemm_kernel<3><<<dim3(16, 392), 256, MG_TOTAL>>>(ga,
            w1 + (size_t)L*1024*256,
            fc1_b + L*1024, nullptr, gb, 1024, 256);
        mgemm_kernel<2><<<dim3(4, 392), 256, MG_TOTAL>>>(gb,
            w2 + (size_t)L*256*1024,
            fc2_b + L*256, gy, nullptr, 256, 1024);
    }

    to_out_kernel<<<dim3(NSPAT/32, CDIM/32, BATCH), 256>>>(gy, out);
}

// round 13
// speedup vs baseline: 2.8154x; 1.0267x over previous
#include <cuda_runtime.h>
#include <cuda_fp16.h>
#include <cstdint>

// ---------------- problem constants ----------------
#define BATCH 2
#define DDIM  8
#define HPX   56
#define WPX   56
#define CDIM  256
#define NTOK  (BATCH*DDIM*HPX*WPX)   // 50176
#define NSPAT (DDIM*HPX*WPX)         // 25088
#define NWIN  98
#define NBIAS 1575
#define MLPD  1024

// ---------------- scratch ----------------
__device__ float g_y  [NTOK*CDIM];        // residual stream, fp32
__device__ __half g_qkvh[NTOK*3*CDIM];    // qkv projections fp16
__device__ __half g_a[NTOK*CDIM];         // activations fp16 (LN out / attn out)
__device__ __half g_b[NTOK*MLPD];         // gelu out (fc2 input)
// transposed fp16 weights: [M_out, K] K-major
__device__ __half w_qkv[4*768*256];
__device__ __half w_out[4*256*256];
__device__ __half w_fc1[4*1024*256];
__device__ __half w_fc2[4*256*1024];

// ---------------- helpers ----------------
__device__ __forceinline__ uint32_t smem_u32(const void* p){
    uint32_t a;
    asm("{ .reg .u64 t; cvta.to.shared.u64 t, %1; cvt.u32.u64 %0, t; }" : "=r"(a) : "l"(p));
    return a;
}
__device__ __forceinline__ void cp16(uint32_t dst, const void* src){
    asm volatile("cp.async.cg.shared.global [%0], [%1], 16;" :: "r"(dst), "l"(src));
}
__device__ __forceinline__ void cp_commit(){
    asm volatile("cp.async.commit_group;" ::: "memory");
}
template<int N>
__device__ __forceinline__ void cp_wait(){
    asm volatile("cp.async.wait_group %0;" :: "n"(N) : "memory");
}
__device__ __forceinline__ void ldsm4(uint32_t addr, uint32_t* r){
    asm volatile("ldmatrix.sync.aligned.m8n8.x4.shared.b16 {%0,%1,%2,%3}, [%4];"
        : "=r"(r[0]), "=r"(r[1]), "=r"(r[2]), "=r"(r[3]) : "r"(addr));
}
__device__ __forceinline__ void ldsm4t(uint32_t addr, uint32_t* r){
    asm volatile("ldmatrix.sync.aligned.m8n8.x4.trans.shared.b16 {%0,%1,%2,%3}, [%4];"
        : "=r"(r[0]), "=r"(r[1]), "=r"(r[2]), "=r"(r[3]) : "r"(addr));
}
__device__ __forceinline__ void mma16816h(float* c, const uint32_t* a, uint32_t b0, uint32_t b1){
    asm volatile("mma.sync.aligned.m16n8k16.row.col.f32.f16.f16.f32 "
        "{%0,%1,%2,%3}, {%4,%5,%6,%7}, {%8,%9}, {%0,%1,%2,%3};"
        : "+f"(c[0]), "+f"(c[1]), "+f"(c[2]), "+f"(c[3])
        : "r"(a[0]), "r"(a[1]), "r"(a[2]), "r"(a[3]), "r"(b0), "r"(b1));
}
__device__ __forceinline__ float gelu_tanh(float x){
    float x3 = x*x*x;
    return 0.5f*x*(1.f + tanhf(0.7978845608028654f*(x + 0.044715f*x3)));
}

// ---------------- weight prep: W[K,M] fp32 -> Wt[M,K] fp16 ----------------
__global__ void wprep_kernel(const float* __restrict__ W, __half* __restrict__ oh,
                             int K, int M)
{
    int ly = blockIdx.y;
    size_t n = (size_t)K*M;
    const float* w = W + ly*n;
    __half* h = oh + ly*n;
    for (size_t i = (size_t)blockIdx.x*blockDim.x + threadIdx.x; i < n; i += (size_t)gridDim.x*blockDim.x){
        int k = (int)(i / M), m = (int)(i % M);
        h[(size_t)m*K + k] = __float2half_rn(w[i]);
    }
}

// ---------------- patch embed ----------------
__global__ void patch_embed_kernel(const float* __restrict__ x,
                                   const float* __restrict__ w,
                                   const float* __restrict__ b,
                                   float* __restrict__ y)
{
    int t = blockIdx.x;
    int wp = t % WPX, hp = (t/WPX) % HPX, d = (t/(WPX*HPX)) % DDIM, bb = t/(WPX*HPX*DDIM);
    __shared__ float patch[64];
    int tid = threadIdx.x;
    if (tid < 64){
        int ic = tid>>4, kh = (tid>>2)&3, kw = tid&3;
        patch[tid] = x[ (((size_t)(bb*4+ic)*DDIM + d)*224 + hp*4+kh)*224 + wp*4+kw ];
    }
    __syncthreads();
    float acc = b[tid];
    const float* wr = w + tid*64;
    #pragma unroll
    for (int k=0;k<64;k++) acc += patch[k]*wr[k];
    y[(size_t)t*CDIM + tid] = acc;
}

// ---------------- layernorm: warp per token, 8 tokens/block, fp16 out ----------------
__global__ void ln_kernel(const float* __restrict__ in,
                          __half* __restrict__ oh,
                          const float* __restrict__ sc, const float* __restrict__ bi)
{
    int warp = threadIdx.x >> 5, lane = threadIdx.x & 31;
    int t = blockIdx.x*8 + warp;
    const float4* row = (const float4*)(in + (size_t)t*CDIM);
    float4 a = row[lane*2], b = row[lane*2+1];
    float s1 = a.x+a.y+a.z+a.w + b.x+b.y+b.z+b.w;
    float s2 = a.x*a.x+a.y*a.y+a.z*a.z+a.w*a.w + b.x*b.x+b.y*b.y+b.z*b.z+b.w*b.w;
    #pragma unroll
    for (int o=16;o;o>>=1){
        s1 += __shfl_xor_sync(0xffffffffu, s1, o);
        s2 += __shfl_xor_sync(0xffffffffu, s2, o);
    }
    float mean = s1*(1.f/256.f);
    float var  = s2*(1.f/256.f) - mean*mean;
    float rs = rsqrtf(var + 1e-5f);
    int c0 = lane*8;
    float4 sca = *(const float4*)(sc + c0), scb = *(const float4*)(sc + c0 + 4);
    float4 bia = *(const float4*)(bi + c0), bib = *(const float4*)(bi + c0 + 4);
    __half2 hh[4];
    hh[0] = __floats2half2_rn((a.x-mean)*rs*sca.x+bia.x, (a.y-mean)*rs*sca.y+bia.y);
    hh[1] = __floats2half2_rn((a.z-mean)*rs*sca.z+bia.z, (a.w-mean)*rs*sca.w+bia.w);
    hh[2] = __floats2half2_rn((b.x-mean)*rs*scb.x+bib.x, (b.y-mean)*rs*scb.y+bib.y);
    hh[3] = __floats2half2_rn((b.z-mean)*rs*scb.z+bib.z, (b.w-mean)*rs*scb.w+bib.w);
    *(uint4*)(oh + (size_t)t*CDIM + c0) = *(uint4*)hh;
}

// ---------------- HMMA fp16 GEMM, 128x128 CTA tile ----------------
// A (act): [NTOK, K] fp16 K-major.  B (weight): [M, K] fp16 K-major.
// CTA: 128 rows x 128 cols, 256 threads = 8 warps (4m x 2n), warp tile 32x64.
// K chunks of 64, double-buffered cp.async; stage = A16K|B16K = 32KB, 2 stages = 64KB -> 2 CTA/SM.
// MODE 0: fp32 out. MODE 2: bias+residual fp32. MODE 3: bias+gelu -> fp16. MODE 4: fp16 out.
#define MG_STAGE 32768
#define MG_TOTAL 65536

template<int MODE>
__global__ void __launch_bounds__(256, 2)
mgemm_kernel(const __half* __restrict__ A,
             const __half* __restrict__ B,
             const float* __restrict__ bias, float* __restrict__ C,
             __half* __restrict__ Oh,
             int M, int K)
{
    extern __shared__ char smem[];
    uint32_t sb = smem_u32(smem);
    int tid = threadIdx.x, lane = tid & 31, wid = tid >> 5;
    int wm = wid & 3, wn = wid >> 2;          // 4m x 2n warp grid
    int row0 = blockIdx.y*128, col0 = blockIdx.x*128;

    const __half* gA = A + (size_t)row0*K;
    const __half* gB = B + (size_t)col0*K;

    float acc[2][8][4];
    #pragma unroll
    for (int i=0;i<2;i++)
        #pragma unroll
        for (int j=0;j<8;j++)
            #pragma unroll
            for (int k=0;k<4;k++) acc[i][j][k]=0.f;

    int lrow = lane & 15, lch = lane >> 4;
    int nchunk = K >> 6;

    // prologue: chunk 0 -> stage 0 (A and B both 128x64 = 1024 uint4 each)
    {
        uint32_t bb = sb;
        #pragma unroll
        for (int h=0; h<4; h++){
            int i = tid + (h<<8);
            int r = i>>3, ch = i&7;
            uint32_t doff = (r<<7) + ((ch ^ (r&7))<<4);
            cp16(bb +         doff, gA + (size_t)r*K + (ch<<3));
            cp16(bb + 16384 + doff, gB + (size_t)r*K + (ch<<3));
        }
        cp_commit();
    }

    #pragma unroll 1
    for (int c = 0; c < nchunk; c++){
        if (c+1 < nchunk){
            int k0 = (c+1) << 6;
            uint32_t bb = sb + ((c+1)&1)*MG_STAGE;
            #pragma unroll
            for (int h=0; h<4; h++){
                int i = tid + (h<<8);
                int r = i>>3, ch = i&7;
                uint32_t doff = (r<<7) + ((ch ^ (r&7))<<4);
                cp16(bb +         doff, gA + (size_t)r*K + k0 + (ch<<3));
                cp16(bb + 16384 + doff, gB + (size_t)r*K + k0 + (ch<<3));
            }
            cp_commit();
            cp_wait<1>();
        } else {
            cp_wait<0>();
        }
        __syncthreads();

        uint32_t tb = sb + (c&1)*MG_STAGE;
        uint32_t tA = tb, tB = tb + 16384;

        #pragma unroll
        for (int ks = 0; ks < 4; ks++){
            int ch0 = ks*2 + lch;
            uint32_t a_f[2][4], b_f[4][4];
            #pragma unroll
            for (int mt=0; mt<2; mt++){
                int row = wm*32 + mt*16 + lrow;
                uint32_t off = (row<<7) + ((ch0 ^ (row&7))<<4);
                ldsm4(tA + off, a_f[mt]);
            }
            #pragma unroll
            for (int np=0; np<4; np++){
                int row = wn*64 + np*16 + lrow;
                uint32_t off = (row<<7) + ((ch0 ^ (row&7))<<4);
                ldsm4(tB + off, b_f[np]);
            }
            #pragma unroll
            for (int mt=0; mt<2; mt++){
                #pragma unroll
                for (int nt=0; nt<8; nt++){
                    int np = nt>>1, hf = nt&1;
                    mma16816h(acc[mt][nt], a_f[mt], b_f[np][hf], b_f[np][hf+2]);
                }
            }
        }
        __syncthreads();
    }

    int lr = lane >> 2, lc = (lane & 3) * 2;
    #pragma unroll
    for (int mt=0; mt<2; mt++){
        #pragma unroll
        for (int nt=0; nt<8; nt++){
            int col = col0 + wn*64 + nt*8 + lc;
            #pragma unroll
            for (int half=0; half<2; half++){
                int row = row0 + wm*32 + mt*16 + lr + half*8;
                float v0 = acc[mt][nt][half*2+0];
                float v1 = acc[mt][nt][half*2+1];
                if (MODE == 0){
                    float2 r; r.x = v0; r.y = v1;
                    *(float2*)(C + (size_t)row*M + col) = r;
                } else if (MODE == 2){
                    float2* cp = (float2*)(C + (size_t)row*M + col);
                    float2 o = *cp;
                    float2 r;
                    r.x = v0 + bias[col+0] + o.x;
                    r.y = v1 + bias[col+1] + o.y;
                    *cp = r;
                } else if (MODE == 4){
                    *(__half2*)(Oh + (size_t)row*M + col) = __floats2half2_rn(v0, v1);
                } else {
                    float a = gelu_tanh(v0 + bias[col+0]);
                    float b = gelu_tanh(v1 + bias[col+1]);
                    *(__half2*)(Oh + (size_t)row*M + col) = __floats2half2_rn(a, b);
                }
            }
        }
    }
}

// ---------------- HMMA flash window attention (fp16 out) ----------------
__global__ void __launch_bounds__(256, 1)
attn_kernel(const __half* __restrict__ qkvh,
            const float* __restrict__ btab_g,
            __half* __restrict__ outh, int shifted)
{
    __shared__ __half Qs[256*40];
    __shared__ __half Ks[64*40];
    __shared__ __half Vs[64*40];
    __shared__ float  btab[NBIAS];
    __shared__ int    sreg[256];

    int head = blockIdx.y;
    int bw = blockIdx.x;
    int b = bw / NWIN, w = bw % NWIN;
    int wd = w/49, wh = (w/7)%7, ww = w%7;
    int tid = threadIdx.x, lane = tid & 31, warp = tid >> 5;
    int lr = lane >> 2, lc = lane & 3;

    {
        int i = tid;
        int di = i>>6, hi = (i>>3)&7, wi = i&7;
        int dr = wd*4+di, hr = wh*8+hi, wr = ww*8+wi;
        int rd = dr<4?0:(dr<6?1:2);
        int rh = hr<48?0:(hr<52?1:2);
        int rw = wr<48?0:(wr<52?1:2);
        sreg[i] = rd*9 + rh*3 + rw;
        int d=dr, h=hr, w2=wr;
        if (shifted){ d=(dr+2)&7; h=(hr+4)%HPX; w2=(wr+4)%WPX; }
        int tok = ((b*DDIM + d)*HPX + h)*WPX + w2;
        const uint4* src = (const uint4*)(qkvh + (size_t)tok*768 + head*32);
        uint4* dst = (uint4*)(Qs + i*40);
        dst[0]=src[0]; dst[1]=src[1]; dst[2]=src[2]; dst[3]=src[3];
    }
    for (int t=tid; t<NBIAS; t+=256) btab[t] = btab_g[t*8 + head];
    __syncthreads();

    uint32_t qbase = smem_u32(Qs), kbase = smem_u32(Ks), vbase = smem_u32(Vs);

    uint32_t qa[2][2][4];
    #pragma unroll
    for (int mt=0; mt<2; mt++)
        #pragma unroll
        for (int kt=0; kt<2; kt++){
            int r = warp*32 + mt*16 + (lane&15);
            ldsm4(qbase + r*80 + (kt*16 + (lane>>4)*8)*2, qa[mt][kt]);
        }

    int rbase0[4], rmyreg[4], rtok[4];
    #pragma unroll
    for (int q=0; q<4; q++){
        int mt = q>>1, hf = q&1;
        int i = warp*32 + mt*16 + lr + hf*8;
        int di = i>>6, hi = (i>>3)&7, wi = i&7;
        int dr = wd*4+di, hr = wh*8+hi, wr = ww*8+wi;
        int rd = dr<4?0:(dr<6?1:2);
        int rh = hr<48?0:(hr<52?1:2);
        int rw = wr<48?0:(wr<52?1:2);
        rmyreg[q] = rd*9 + rh*3 + rw;
        rbase0[q] = (di+3)*225 + (hi+7)*15 + (wi+7);
        int d=dr, h=hr, w2=wr;
        if (shifted){ d=(dr+2)&7; h=(hr+4)%HPX; w2=(wr+4)%WPX; }
        rtok[q] = ((b*DDIM + d)*HPX + h)*WPX + w2;
    }

    float mrow[4], lrow[4];
    #pragma unroll
    for (int q=0; q<4; q++){ mrow[q] = -1e30f; lrow[q] = 0.f; }
    float o[2][4][4];
    #pragma unroll
    for (int mt=0; mt<2; mt++)
        #pragma unroll
        for (int nt=0; nt<4; nt++)
            #pragma unroll
            for (int k=0;k<4;k++) o[mt][nt][k] = 0.f;

    const float scale = 0.17677669529663687f;

    #pragma unroll 1
    for (int c = 0; c < 4; c++){
        __syncthreads();
        {
            int r = tid>>2, part = tid&3;
            int j = c*64 + r;
            int hi = (j>>3)&7, wi = j&7;
            int dr = wd*4+c, hr = wh*8+hi, wr = ww*8+wi;
            int d=dr, h=hr, w2=wr;
            if (shifted){ d=(dr+2)&7; h=(hr+4)%HPX; w2=(wr+4)%WPX; }
            int tok = ((b*DDIM + d)*HPX + h)*WPX + w2;
            const uint4* kv = (const uint4*)(qkvh + (size_t)tok*768 + 256 + head*32);
            const uint4* vv = (const uint4*)(qkvh + (size_t)tok*768 + 512 + head*32);
            *(uint4*)(Ks + r*40 + part*8) = kv[part];
            *(uint4*)(Vs + r*40 + part*8) = vv[part];
        }
        __syncthreads();

        float S[2][8][4];
        #pragma unroll
        for (int mt=0;mt<2;mt++)
            #pragma unroll
            for (int jt=0;jt<8;jt++)
                #pragma unroll
                for (int k=0;k<4;k++) S[mt][jt][k]=0.f;

        #pragma unroll
        for (int p=0; p<4; p++){
            uint32_t kf[2][4];
            #pragma unroll
            for (int kt=0; kt<2; kt++){
                int r = p*16 + (lane&15);
                ldsm4(kbase + r*80 + (kt*16 + (lane>>4)*8)*2, kf[kt]);
            }
            #pragma unroll
            for (int mt=0; mt<2; mt++)
                #pragma unroll
                for (int s=0; s<2; s++)
                    #pragma unroll
                    for (int kt=0; kt<2; kt++)
                        mma16816h(S[mt][p*2+s], qa[mt][kt], kf[kt][s], kf[kt][s+2]);
        }

        float mc[4];
        #pragma unroll
        for (int q=0;q<4;q++) mc[q] = -1e30f;
        #pragma unroll
        for (int mt=0; mt<2; mt++)
            #pragma unroll
            for (int jt=0; jt<8; jt++)
                #pragma unroll
                for (int idx=0; idx<4; idx++){
                    int q = mt*2 + (idx>>1);
                    int e = idx&1;
                    int rel = rbase0[q] - c*225 - jt*15 - (2*lc + e);
                    float s = fmaf(S[mt][jt][idx], scale, btab[rel]);
                    if (shifted && sreg[c*64 + jt*8 + 2*lc + e] != rmyreg[q]) s = -1e9f;
                    S[mt][jt][idx] = s;
                    mc[q] = fmaxf(mc[q], s);
                }
        #pragma unroll
        for (int q=0;q<4;q++){
            mc[q] = fmaxf(mc[q], __shfl_xor_sync(0xffffffffu, mc[q], 1));
            mc[q] = fmaxf(mc[q], __shfl_xor_sync(0xffffffffu, mc[q], 2));
        }

        float corr[4], sumc[4];
        #pragma unroll
        for (int q=0;q<4;q++){
            float mn = fmaxf(mrow[q], mc[q]);
            corr[q] = __expf(mrow[q] - mn);
            mrow[q] = mn;
            sumc[q] = 0.f;
        }
        uint32_t pa[2][4][4];
        #pragma unroll
        for (int mt=0; mt<2; mt++)
            #pragma unroll
            for (int kt2=0; kt2<4; kt2++){
                int jtA = kt2*2, jtB = kt2*2+1;
                float pA0 = __expf(S[mt][jtA][0]-mrow[mt*2]);
                float pA1 = __expf(S[mt][jtA][1]-mrow[mt*2]);
                float pA2 = __expf(S[mt][jtA][2]-mrow[mt*2+1]);
                float pA3 = __expf(S[mt][jtA][3]-mrow[mt*2+1]);
                float pB0 = __expf(S[mt][jtB][0]-mrow[mt*2]);
                float pB1 = __expf(S[mt][jtB][1]-mrow[mt*2]);
                float pB2 = __expf(S[mt][jtB][2]-mrow[mt*2+1]);
                float pB3 = __expf(S[mt][jtB][3]-mrow[mt*2+1]);
                sumc[mt*2+0] += pA0 + pA1 + pB0 + pB1;
                sumc[mt*2+1] += pA2 + pA3 + pB2 + pB3;
                __half2 a0 = __floats2half2_rn(pA0, pA1);
                __half2 a1 = __floats2half2_rn(pA2, pA3);
                __half2 a2 = __floats2half2_rn(pB0, pB1);
                __half2 a3 = __floats2half2_rn(pB2, pB3);
                pa[mt][kt2][0] = *(uint32_t*)&a0;
                pa[mt][kt2][1] = *(uint32_t*)&a1;
                pa[mt][kt2][2] = *(uint32_t*)&a2;
                pa[mt][kt2][3] = *(uint32_t*)&a3;
            }
        #pragma unroll
        for (int q=0;q<4;q++){
            sumc[q] += __shfl_xor_sync(0xffffffffu, sumc[q], 1);
            sumc[q] += __shfl_xor_sync(0xffffffffu, sumc[q], 2);
            lrow[q] = lrow[q]*corr[q] + sumc[q];
        }
        #pragma unroll
        for (int mt=0; mt<2; mt++)
            #pragma unroll
            for (int nt=0; nt<4; nt++){
                o[mt][nt][0] *= corr[mt*2+0];
                o[mt][nt][1] *= corr[mt*2+0];
                o[mt][nt][2] *= corr[mt*2+1];
                o[mt][nt][3] *= corr[mt*2+1];
            }

        #pragma unroll
        for (int dp=0; dp<2; dp++){
            uint32_t vl[4][4];
            #pragma unroll
            for (int kt2=0; kt2<4; kt2++){
                uint32_t addr = vbase + (kt2*16 + ((lane>>3)&1)*8 + (lane&7))*80
                              + (dp*16 + (lane>>4)*8)*2;
                ldsm4t(addr, vl[kt2]);
            }
            #pragma unroll
            for (int s=0; s<2; s++){
                int nt = dp*2 + s;
                #pragma unroll
                for (int mt=0; mt<2; mt++)
                    #pragma unroll
                    for (int kt2=0; kt2<4; kt2++)
                        mma16816h(o[mt][nt], pa[mt][kt2], vl[kt2][2*s], vl[kt2][2*s+1]);
            }
        }
    }

    float inv[4];
    #pragma unroll
    for (int q=0;q<4;q++) inv[q] = 1.f/lrow[q];
    #pragma unroll
    for (int mt=0; mt<2; mt++)
        #pragma unroll
        for (int nt=0; nt<4; nt++){
            int col = head*32 + nt*8 + 2*lc;
            #pragma unroll
            for (int hf=0; hf<2; hf++){
                int q = mt*2 + hf;
                float v0 = o[mt][nt][hf*2+0]*inv[q];
                float v1 = o[mt][nt][hf*2+1]*inv[q];
                *(__half2*)(outh + (size_t)rtok[q]*CDIM + col) = __floats2half2_rn(v0, v1);
            }
        }
}

// ---------------- final transpose: tiled, coalesced ----------------
__global__ void to_out_kernel(const float* __restrict__ y, float* __restrict__ out)
{
    __shared__ float tile[32][33];
    int b = blockIdx.z;
    int c0 = blockIdx.y*32, s0 = blockIdx.x*32;
    int tx = threadIdx.x & 31, ty = threadIdx.x >> 5;
    #pragma unroll
    for (int i=0;i<4;i++)
        tile[ty + i*8][tx] = y[((size_t)b*NSPAT + s0 + ty + i*8)*CDIM + c0 + tx];
    __syncthreads();
    #pragma unroll
    for (int i=0;i<4;i++)
        out[((size_t)(b*CDIM + c0 + ty + i*8))*NSPAT + s0 + tx] = tile[tx][ty + i*8];
}

// ---------------- launch ----------------
extern "C" void kernel_launch(void* const* d_in, const int* in_sizes, int n_in,
                              void* d_out, int out_size)
{
    const float* x      = (const float*)d_in[0];
    const float* conv_w = (const float*)d_in[1];
    const float* conv_b = (const float*)d_in[2];
    const float* ln1_s  = (const float*)d_in[3];
    const float* ln1_b  = (const float*)d_in[4];
    const float* qkv_w  = (const float*)d_in[5];
    const float* out_w  = (const float*)d_in[6];
    const float* out_b  = (const float*)d_in[7];
    const float* bias_t = (const float*)d_in[8];
    const float* ln2_s  = (const float*)d_in[9];
    const float* ln2_b  = (const float*)d_in[10];
    const float* fc1_w  = (const float*)d_in[11];
    const float* fc1_b  = (const float*)d_in[12];
    const float* fc2_w  = (const float*)d_in[13];
    const float* fc2_b  = (const float*)d_in[14];
    float* out = (float*)d_out;

    cudaFuncSetAttribute(mgemm_kernel<0>, cudaFuncAttributeMaxDynamicSharedMemorySize, MG_TOTAL);
    cudaFuncSetAttribute(mgemm_kernel<2>, cudaFuncAttributeMaxDynamicSharedMemorySize, MG_TOTAL);
    cudaFuncSetAttribute(mgemm_kernel<3>, cudaFuncAttributeMaxDynamicSharedMemorySize, MG_TOTAL);
    cudaFuncSetAttribute(mgemm_kernel<4>, cudaFuncAttributeMaxDynamicSharedMemorySize, MG_TOTAL);

    float *gy;
    __half *gqkvh, *ga, *gb;
    __half *wq, *wo, *w1, *w2;
    cudaGetSymbolAddress((void**)&gy,    g_y);
    cudaGetSymbolAddress((void**)&gqkvh, g_qkvh);
    cudaGetSymbolAddress((void**)&ga,    g_a);
    cudaGetSymbolAddress((void**)&gb,    g_b);
    cudaGetSymbolAddress((void**)&wq,    w_qkv);
    cudaGetSymbolAddress((void**)&wo,    w_out);
    cudaGetSymbolAddress((void**)&w1,    w_fc1);
    cudaGetSymbolAddress((void**)&w2,    w_fc2);

    wprep_kernel<<<dim3(512,4), 256>>>(qkv_w, wq, 256, 768);
    wprep_kernel<<<dim3(512,4), 256>>>(out_w, wo, 256, 256);
    wprep_kernel<<<dim3(512,4), 256>>>(fc1_w, w1, 256, 1024);
    wprep_kernel<<<dim3(512,4), 256>>>(fc2_w, w2, 1024, 256);

    patch_embed_kernel<<<NTOK, 256>>>(x, conv_w, conv_b, gy);

    for (int L=0; L<4; L++){
        int shifted = L & 1;
        ln_kernel<<<NTOK/8, 256>>>(gy, ga, ln1_s + L*256, ln1_b + L*256);
        mgemm_kernel<4><<<dim3(6, 392), 256, MG_TOTAL>>>(ga,
            wq + (size_t)L*768*256,
            nullptr, nullptr, gqkvh, 768, 256);
        attn_kernel<<<dim3(BATCH*NWIN, 8), 256>>>(gqkvh, bias_t + (size_t)L*NBIAS*8, ga, shifted);
        mgemm_kernel<2><<<dim3(2, 392), 256, MG_TOTAL>>>(ga,
            wo + (size_t)L*256*256,
            out_b + L*256, gy, nullptr, 256, 256);
        ln_kernel<<<NTOK/8, 256>>>(gy, ga, ln2_s + L*256, ln2_b + L*256);
        mgemm_kernel<3><<<dim3(8, 392), 256, MG_TOTAL>>>(ga,
            w1 + (size_t)L*1024*256,
            fc1_b + L*1024, nullptr, gb, 1024, 256);
        mgemm_kernel<2><<<dim3(2, 392), 256, MG_TOTAL>>>(gb,
            w2 + (size_t)L*256*1024,
            fc2_b + L*256, gy, nullptr, 256, 1024);
    }

    to_out_kernel<<<dim3(NSPAT/32, CDIM/32, BATCH), 256>>>(gy, out);
}